// round 7
// baseline (speedup 1.0000x reference)
#include <cuda_runtime.h>
#include <cuda_bf16.h>
#include <cstdint>

#define NN 128
#define LL 256
#define CM 256
#define CH 32
#define CZ 128
#define RTOT 8192   // LL*CH

// ---------------- global scratch ----------------
__device__ __align__(16) __nv_bfloat16 g_Ah[RTOT * NN];   // [r=i*32+c][n]
__device__ __align__(16) __nv_bfloat16 g_Al[RTOT * NN];
__device__ __align__(16) __nv_bfloat16 g_Bh[RTOT * NN];
__device__ __align__(16) __nv_bfloat16 g_Bl[RTOT * NN];
__device__ __align__(16) __nv_bfloat16 g_Woh[CZ * 1024];  // [z][k] (Wo^T)
__device__ __align__(16) __nv_bfloat16 g_Wol[CZ * 1024];
__device__ float g_pm[LL * LL];
// O in bf16 hi/lo, layout [pair = i*256+j][k = c*32+d]
__device__ __align__(16) __nv_bfloat16 g_Oh[(size_t)65536 * 1024];   // 128 MB
__device__ __align__(16) __nv_bfloat16 g_Ol[(size_t)65536 * 1024];   // 128 MB

// ---------------- helpers ----------------
__device__ __forceinline__ uint32_t smem_u32(const void* p) {
    uint32_t a;
    asm("{ .reg .u64 t; cvta.to.shared.u64 t, %1; cvt.u32.u64 %0, t; }" : "=r"(a) : "l"(p));
    return a;
}
__device__ __forceinline__ void ldsm4(uint32_t* r, uint32_t addr) {
    asm volatile("ldmatrix.sync.aligned.m8n8.x4.shared.b16 {%0,%1,%2,%3}, [%4];"
        : "=r"(r[0]), "=r"(r[1]), "=r"(r[2]), "=r"(r[3]) : "r"(addr));
}
__device__ __forceinline__ void mma_bf16(float* d, const uint32_t* a,
                                         uint32_t b0, uint32_t b1) {
    asm volatile(
        "mma.sync.aligned.m16n8k16.row.col.f32.bf16.bf16.f32 "
        "{%0,%1,%2,%3}, {%4,%5,%6,%7}, {%8,%9}, {%0,%1,%2,%3};"
        : "+f"(d[0]), "+f"(d[1]), "+f"(d[2]), "+f"(d[3])
        : "r"(a[0]), "r"(a[1]), "r"(a[2]), "r"(a[3]), "r"(b0), "r"(b1));
}
#define CP16(dst, src) asm volatile("cp.async.cg.shared.global [%0], [%1], 16;" :: "r"(dst), "l"(src))
#define CP_COMMIT()    asm volatile("cp.async.commit_group;" ::: "memory")
#define CP_WAIT(n)     asm volatile("cp.async.wait_group %0;" :: "n"(n) : "memory")

__device__ __forceinline__ void split1(float x, __nv_bfloat16& h, __nv_bfloat16& l) {
    h = __float2bfloat16(x);
    l = __float2bfloat16(x - __bfloat162float(h));
}

// ---------------------------------------------------------------------------
// Kernel 1: LayerNorm + projections -> bf16 hi/lo, layout [i*32+h][n]
// ---------------------------------------------------------------------------
__global__ __launch_bounds__(256) void ln_proj_kernel(
    const float* __restrict__ m, const float* __restrict__ mask,
    const float* __restrict__ gamma, const float* __restrict__ beta,
    const float* __restrict__ Wa, const float* __restrict__ ba,
    const float* __restrict__ Wb, const float* __restrict__ bb)
{
    extern __shared__ float sm1[];
    float* sWa  = sm1;
    float* sWb  = sWa + 8192;
    float* xs   = sWb + 8192;
    float* sred = xs + 256;
    float* scr  = sred + 256;
    __nv_bfloat16* sStage = (__nv_bfloat16*)(scr + 16);

    const int tid = threadIdx.x;
    for (int l = tid; l < 8192; l += 256) { sWa[l] = Wa[l]; sWb[l] = Wb[l]; }
    __syncthreads();

    const float gam = gamma[tid];
    const float bet = beta[tid];

    const int outp = tid & 63;
    const int part = tid >> 6;
    const int h    = outp & 31;
    const float* W = (outp < 32) ? sWa : sWb;

    const int nb = blockIdx.x >> 7;
    const int ib = blockIdx.x & 127;
    const int n0 = nb * 16;
    const int i0 = ib * 2;

    for (int rr = 0; rr < 32; rr++) {
        const int n_loc = rr & 15;
        const int i_loc = rr >> 4;
        const int row = (n0 + n_loc) * LL + (i0 + i_loc);

        const float xv = m[row * CM + tid];
        float a = xv, b = xv * xv;
#pragma unroll
        for (int o = 16; o > 0; o >>= 1) {
            a += __shfl_xor_sync(0xffffffffu, a, o);
            b += __shfl_xor_sync(0xffffffffu, b, o);
        }
        if ((tid & 31) == 0) { scr[tid >> 5] = a; scr[8 + (tid >> 5)] = b; }
        __syncthreads();
        if (tid < 32) {
            float x = (tid < 8) ? scr[tid] : 0.f;
            float y = (tid < 8) ? scr[8 + tid] : 0.f;
#pragma unroll
            for (int o = 4; o > 0; o >>= 1) {
                x += __shfl_xor_sync(0xffffffffu, x, o);
                y += __shfl_xor_sync(0xffffffffu, y, o);
            }
            if (tid == 0) { scr[0] = x; scr[8] = y; }
        }
        __syncthreads();
        const float mean = scr[0] * (1.f / 256.f);
        const float msq  = scr[8] * (1.f / 256.f);
        __syncthreads();
        const float var = msq - mean * mean;

        xs[tid] = (xv - mean) * rsqrtf(var + 1e-5f) * gam + bet;
        __syncthreads();

        float s = 0.f;
#pragma unroll
        for (int kk = 0; kk < 64; kk++) {
            const int k = part * 64 + kk;
            s += xs[k] * W[k * 32 + h];
        }
        sred[tid] = s;
        __syncthreads();

        if (tid < 64) {
            float tot = sred[tid] + sred[tid + 64] + sred[tid + 128] + sred[tid + 192];
            const float mk = mask[row];
            const int sidx = (i_loc * 32 + h) * 16 + n_loc;
            __nv_bfloat16 hi, lo;
            if (tid < 32) {
                split1((tot + ba[h]) * mk, hi, lo);
                sStage[0 * 1024 + sidx] = hi;
                sStage[1 * 1024 + sidx] = lo;
            } else {
                split1((tot + bb[h]) * mk, hi, lo);
                sStage[2 * 1024 + sidx] = hi;
                sStage[3 * 1024 + sidx] = lo;
            }
        }
        __syncthreads();
    }

#pragma unroll
    for (int v = 0; v < 2; v++) {
        const int fidx = v * 256 + tid;
        const int arr  = fidx >> 7;
        const int rem  = fidx & 127;
        const int il   = rem >> 6;
        const int hh   = (rem >> 1) & 31;
        const int half = rem & 1;
        const uint4 val = *reinterpret_cast<const uint4*>(
            sStage + arr * 1024 + (il * 32 + hh) * 16 + half * 8);
        __nv_bfloat16* gdst = (arr == 0) ? g_Ah : (arr == 1) ? g_Al : (arr == 2) ? g_Bh : g_Bl;
        reinterpret_cast<uint4*>(gdst)[((i0 + il) * 32 + hh) * 16 + nb * 2 + half] = val;
    }
}

// ---------------------------------------------------------------------------
// Prep: pair mask table + Wo^T bf16 split
// ---------------------------------------------------------------------------
__global__ __launch_bounds__(256) void prep_kernel(
    const float* __restrict__ mask, const float* __restrict__ Wo)
{
    if (blockIdx.x < 256) {
        const int i = blockIdx.x, j = threadIdx.x;
        float s = 0.f;
        for (int n = 0; n < NN; n++) s += mask[n * LL + i] * mask[n * LL + j];
        g_pm[i * LL + j] = s;
    } else {
        const int b = blockIdx.x - 256;
#pragma unroll
        for (int v = 0; v < 8; v++) {
            const int e = b * 2048 + v * 256 + threadIdx.x;
            const float val = Wo[e];
            const int k = e >> 7, z = e & 127;
            __nv_bfloat16 hi, lo;
            split1(val, hi, lo);
            g_Woh[z * 1024 + k] = hi;
            g_Wol[z * 1024 + k] = lo;
        }
    }
}

// ---------------------------------------------------------------------------
// mma1: O = A^T B (tiles 128x128, K=128). Persistent over bn:
// CTA = (group g, bm); A tile loaded once, loops bn = g*8..g*8+7 with
// double-buffered B cp.async. Epilogue staged via B[st] smem -> contiguous STG.
// SMEM: A 2x34816 | B 2 stages x 2 bufs x 34816  = 208,896 B
// ---------------------------------------------------------------------------
#define M1_AH   0
#define M1_AL   34816
#define M1_B(st, buf) (69632 + (st) * 69632 + (buf) * 34816)
#define M1_SMEM 208896

__global__ __launch_bounds__(512) void mma1_kernel()
{
    extern __shared__ char smem[];
    const uint32_t sb = smem_u32(smem);
    const int tid  = threadIdx.x;
    const int lane = tid & 31;
    const int wid  = tid >> 5;
    const int wm   = wid >> 2, wn = wid & 3;
    const int g  = blockIdx.x;   // 0..7
    const int bm = blockIdx.y;   // 0..63

    // group A: Ah+Al, 2 bufs x 128 rows x 256B
#pragma unroll
    for (int v = 0; v < 8; v++) {
        const int idx = v * 512 + tid;
        const int buf = idx >> 11;
        const int rem = idx & 2047;
        const int row = rem >> 4, q = rem & 15;
        const __nv_bfloat16* src = buf ? g_Al : g_Ah;
        CP16(sb + (buf ? M1_AL : M1_AH) + row * 272 + q * 16,
             src + (size_t)(bm * 128 + row) * 128 + q * 8);
    }
    CP_COMMIT();

    // groups B0, B1
#pragma unroll
    for (int pre = 0; pre < 2; pre++) {
        const int bn = g * 8 + pre;
#pragma unroll
        for (int v = 0; v < 8; v++) {
            const int idx = v * 512 + tid;
            const int buf = idx >> 11;
            const int rem = idx & 2047;
            const int row = rem >> 4, q = rem & 15;
            const __nv_bfloat16* src = buf ? g_Bl : g_Bh;
            CP16(sb + M1_B(pre, buf) + row * 272 + q * 16,
                 src + (size_t)(bn * 128 + row) * 128 + q * 8);
        }
        CP_COMMIT();
    }

    const uint32_t rofs = (uint32_t)((lane & 15) * 272 + (lane >> 4) * 16);
    const uint32_t aAh = sb + M1_AH + wm * 32 * 272 + rofs;
    const uint32_t aAl = sb + M1_AL + wm * 32 * 272 + rofs;

    CP_WAIT(1);          // A + B0 done, B1 in flight
    __syncthreads();

    for (int it = 0; it < 8; it++) {
        const int st = it & 1;
        const int bn = g * 8 + it;
        const uint32_t aBh = sb + M1_B(st, 0) + wn * 32 * 272 + rofs;
        const uint32_t aBl = sb + M1_B(st, 1) + wn * 32 * 272 + rofs;

        float acc[2][4][4];
#pragma unroll
        for (int fm = 0; fm < 2; fm++)
#pragma unroll
            for (int fn = 0; fn < 4; fn++)
#pragma unroll
                for (int e = 0; e < 4; e++) acc[fm][fn][e] = 0.f;

#pragma unroll
        for (int ks = 0; ks < 8; ks++) {
            uint32_t A_h[2][4], A_l[2][4], B_h[2][4], B_l[2][4];
            ldsm4(A_h[0], aAh + ks * 32);
            ldsm4(A_h[1], aAh + 16 * 272 + ks * 32);
            ldsm4(A_l[0], aAl + ks * 32);
            ldsm4(A_l[1], aAl + 16 * 272 + ks * 32);
            ldsm4(B_h[0], aBh + ks * 32);
            ldsm4(B_h[1], aBh + 16 * 272 + ks * 32);
            ldsm4(B_l[0], aBl + ks * 32);
            ldsm4(B_l[1], aBl + 16 * 272 + ks * 32);
#pragma unroll
            for (int fm = 0; fm < 2; fm++)
#pragma unroll
                for (int fn = 0; fn < 4; fn++) {
                    const uint32_t bh0 = B_h[fn >> 1][fn & 1];
                    const uint32_t bh1 = B_h[fn >> 1][(fn & 1) + 2];
                    const uint32_t bl0 = B_l[fn >> 1][fn & 1];
                    const uint32_t bl1 = B_l[fn >> 1][(fn & 1) + 2];
                    mma_bf16(acc[fm][fn], A_h[fm], bh0, bh1);
                    mma_bf16(acc[fm][fn], A_h[fm], bl0, bl1);
                    mma_bf16(acc[fm][fn], A_l[fm], bh0, bh1);
                }
        }

        __syncthreads();   // compute on B[st] done everywhere

        // stage pair data into B[st] region: pair p=wid -> h @ p*4096, l @ +2048
        char* ep = smem + M1_B(st, 0);
#pragma unroll
        for (int fm = 0; fm < 2; fm++)
#pragma unroll
            for (int fn = 0; fn < 4; fn++)
#pragma unroll
                for (int half = 0; half < 2; half++) {
                    const int c = (lane >> 2) + half * 8 + fm * 16;
                    const int k = c * 32 + (lane & 3) * 2 + fn * 8;
                    __nv_bfloat162 h2, l2;
                    split1(acc[fm][fn][half * 2 + 0], h2.x, l2.x);
                    split1(acc[fm][fn][half * 2 + 1], h2.y, l2.y);
                    *reinterpret_cast<__nv_bfloat162*>(ep + wid * 4096 + 2 * k) = h2;
                    *reinterpret_cast<__nv_bfloat162*>(ep + wid * 4096 + 2048 + 2 * k) = l2;
                }
        __syncthreads();   // staging complete

        // contiguous STG: warp p writes its pair's 2KB (h) + 2KB (l)
        {
            const int p = wid;
            const int i_g = bm * 4 + (p >> 2);
            const int j_g = bn * 4 + (p & 3);
            const size_t bg = (size_t)(i_g * 256 + j_g) * 1024;
            const char* s = ep + p * 4096 + lane * 64;
#pragma unroll
            for (int q = 0; q < 4; q++) {
                const uint4 hv = *reinterpret_cast<const uint4*>(s + q * 16);
                const uint4 lv = *reinterpret_cast<const uint4*>(s + 2048 + q * 16);
                *reinterpret_cast<uint4*>(
                    reinterpret_cast<char*>(g_Oh + bg) + lane * 64 + q * 16) = hv;
                *reinterpret_cast<uint4*>(
                    reinterpret_cast<char*>(g_Ol + bg) + lane * 64 + q * 16) = lv;
            }
        }
        __syncthreads();   // LDS of ep done -> B[st] reusable

        if (it + 2 < 8) {
            const int bn2 = g * 8 + it + 2;
#pragma unroll
            for (int v = 0; v < 8; v++) {
                const int idx = v * 512 + tid;
                const int buf = idx >> 11;
                const int rem = idx & 2047;
                const int row = rem >> 4, q = rem & 15;
                const __nv_bfloat16* src = buf ? g_Bl : g_Bh;
                CP16(sb + M1_B(st, buf) + row * 272 + q * 16,
                     src + (size_t)(bn2 * 128 + row) * 128 + q * 8);
            }
            CP_COMMIT();
            CP_WAIT(1);    // B[it+1] done, B[it+2] in flight
        } else {
            CP_WAIT(0);    // drain (ensures B[it+1] for it==6)
        }
        __syncthreads();   // visibility of B[it+1] to all
    }
}

// ---------------------------------------------------------------------------
// mma2: Z = O @ Wo^T.  M=128 pairs, N=128, K=1024. 3-stage cp.async pipeline,
// one __syncthreads per chunk.  SMEM: 3 stages x 4 bufs x 18432 = 221,184 B
// ---------------------------------------------------------------------------
#define S2_BUF   18432
#define S2_STAGE 73728
#define S2_SMEM  221184

__device__ __forceinline__ void mma2_load_chunk(uint32_t sb, int st, int ck,
                                                int tid, size_t pairbase)
{
#pragma unroll
    for (int v = 0; v < 8; v++) {
        const int idx = v * 512 + tid;
        const int buf = idx >> 10;
        const int rem = idx & 1023;
        const int row = rem >> 3, q = rem & 7;
        const __nv_bfloat16* src;
        if (buf == 0)      src = g_Oh + (pairbase + row) * 1024 + ck * 64 + q * 8;
        else if (buf == 1) src = g_Ol + (pairbase + row) * 1024 + ck * 64 + q * 8;
        else if (buf == 2) src = g_Woh + (size_t)row * 1024 + ck * 64 + q * 8;
        else               src = g_Wol + (size_t)row * 1024 + ck * 64 + q * 8;
        CP16(sb + st * S2_STAGE + buf * S2_BUF + row * 144 + q * 16, src);
    }
    CP_COMMIT();
}

__global__ __launch_bounds__(512) void mma2_kernel(
    const float* __restrict__ bo, float* __restrict__ out)
{
    extern __shared__ char smem[];
    const uint32_t sb = smem_u32(smem);
    const int tid = threadIdx.x;
    const int i  = blockIdx.x >> 1;
    const int j0 = (blockIdx.x & 1) * 128;
    const size_t pairbase = (size_t)i * 256 + j0;

    const int lane = tid & 31;
    const int wid  = tid >> 5;
    const int wm = wid >> 2, wn = wid & 3;

    float acc[2][4][4];
#pragma unroll
    for (int fm = 0; fm < 2; fm++)
#pragma unroll
        for (int fn = 0; fn < 4; fn++)
#pragma unroll
            for (int e = 0; e < 4; e++) acc[fm][fn][e] = 0.f;

    const uint32_t rofs = (uint32_t)((lane & 15) * 144 + (lane >> 4) * 16);

    mma2_load_chunk(sb, 0, 0, tid, pairbase);
    mma2_load_chunk(sb, 1, 1, tid, pairbase);

    for (int ck = 0; ck < 16; ck++) {
        const int st = ck % 3;
        if (ck < 15) CP_WAIT(1); else CP_WAIT(0);
        __syncthreads();   // chunk ck visible; iter ck-1 compute retired

        if (ck + 2 < 16)
            mma2_load_chunk(sb, (ck + 2) % 3, ck + 2, tid, pairbase);

        const uint32_t base = sb + st * S2_STAGE;
        const uint32_t aAh = base + 0 * S2_BUF + wm * 32 * 144 + rofs;
        const uint32_t aAl = base + 1 * S2_BUF + wm * 32 * 144 + rofs;
        const uint32_t aBh = base + 2 * S2_BUF + wn * 32 * 144 + rofs;
        const uint32_t aBl = base + 3 * S2_BUF + wn * 32 * 144 + rofs;

#pragma unroll
        for (int ks = 0; ks < 4; ks++) {
            uint32_t A_h[2][4], A_l[2][4], B_h[2][4], B_l[2][4];
            ldsm4(A_h[0], aAh + ks * 32);
            ldsm4(A_h[1], aAh + 16 * 144 + ks * 32);
            ldsm4(A_l[0], aAl + ks * 32);
            ldsm4(A_l[1], aAl + 16 * 144 + ks * 32);
            ldsm4(B_h[0], aBh + ks * 32);
            ldsm4(B_h[1], aBh + 16 * 144 + ks * 32);
            ldsm4(B_l[0], aBl + ks * 32);
            ldsm4(B_l[1], aBl + 16 * 144 + ks * 32);
#pragma unroll
            for (int fm = 0; fm < 2; fm++)
#pragma unroll
                for (int fn = 0; fn < 4; fn++) {
                    const uint32_t bh0 = B_h[fn >> 1][fn & 1];
                    const uint32_t bh1 = B_h[fn >> 1][(fn & 1) + 2];
                    const uint32_t bl0 = B_l[fn >> 1][fn & 1];
                    const uint32_t bl1 = B_l[fn >> 1][(fn & 1) + 2];
                    mma_bf16(acc[fm][fn], A_h[fm], bh0, bh1);
                    mma_bf16(acc[fm][fn], A_h[fm], bl0, bl1);
                    mma_bf16(acc[fm][fn], A_l[fm], bh0, bh1);
                }
        }
    }

    const int jl0 = wm * 32 + (lane >> 2);
    const int z0  = wn * 32 + (lane & 3) * 2;
#pragma unroll
    for (int fm = 0; fm < 2; fm++) {
#pragma unroll
        for (int half = 0; half < 2; half++) {
            const int jl = jl0 + fm * 16 + half * 8;
            const int j = j0 + jl;
            const float inv = 1.f / (g_pm[i * LL + j] + 1e-8f);
#pragma unroll
            for (int fn = 0; fn < 4; fn++) {
                const int z = z0 + fn * 8;
                float2 res;
                res.x = acc[fm][fn][half * 2 + 0] * inv + bo[z];
                res.y = acc[fm][fn][half * 2 + 1] * inv + bo[z + 1];
                *reinterpret_cast<float2*>(out + (size_t)(i * LL + j) * CZ + z) = res;
            }
        }
    }
}

// ---------------------------------------------------------------------------
extern "C" void kernel_launch(void* const* d_in, const int* in_sizes, int n_in,
                              void* d_out, int out_size)
{
    const float* m     = (const float*)d_in[0];
    const float* mask  = (const float*)d_in[1];
    const float* gamma = (const float*)d_in[2];
    const float* beta  = (const float*)d_in[3];
    const float* Wa    = (const float*)d_in[4];
    const float* ba    = (const float*)d_in[5];
    const float* Wb    = (const float*)d_in[6];
    const float* bb    = (const float*)d_in[7];
    const float* Wo    = (const float*)d_in[8];
    const float* bo    = (const float*)d_in[9];
    float* out = (float*)d_out;

    const int smem1 = 16912 * 4 + 4096 * 2;
    cudaFuncSetAttribute(ln_proj_kernel, cudaFuncAttributeMaxDynamicSharedMemorySize, smem1);
    cudaFuncSetAttribute(mma1_kernel,    cudaFuncAttributeMaxDynamicSharedMemorySize, M1_SMEM);
    cudaFuncSetAttribute(mma2_kernel,    cudaFuncAttributeMaxDynamicSharedMemorySize, S2_SMEM);

    ln_proj_kernel<<<1024, 256, smem1>>>(m, mask, gamma, beta, Wa, ba, Wb, bb);
    prep_kernel<<<320, 256>>>(mask, Wo);
    mma1_kernel<<<dim3(8, 64), 512, M1_SMEM>>>();
    mma2_kernel<<<512, 512, S2_SMEM>>>(bo, out);
}

// round 8
// speedup vs baseline: 1.1277x; 1.1277x over previous
#include <cuda_runtime.h>
#include <cuda_bf16.h>
#include <cstdint>

#define NN 128
#define LL 256
#define CM 256
#define CH 32
#define CZ 128
#define RTOT 8192   // LL*CH

// ---------------- global scratch ----------------
__device__ __align__(16) __nv_bfloat16 g_Ah[RTOT * NN];   // [r=i*32+c][n]
__device__ __align__(16) __nv_bfloat16 g_Al[RTOT * NN];
__device__ __align__(16) __nv_bfloat16 g_Bh[RTOT * NN];
__device__ __align__(16) __nv_bfloat16 g_Bl[RTOT * NN];
__device__ __align__(16) __nv_bfloat16 g_Woh[CZ * 1024];  // [z][k] (Wo^T)
__device__ __align__(16) __nv_bfloat16 g_Wol[CZ * 1024];
__device__ float g_pm[LL * LL];

// ---------------- helpers ----------------
__device__ __forceinline__ uint32_t smem_u32(const void* p) {
    uint32_t a;
    asm("{ .reg .u64 t; cvta.to.shared.u64 t, %1; cvt.u32.u64 %0, t; }" : "=r"(a) : "l"(p));
    return a;
}
__device__ __forceinline__ void ldsm4(uint32_t* r, uint32_t addr) {
    asm volatile("ldmatrix.sync.aligned.m8n8.x4.shared.b16 {%0,%1,%2,%3}, [%4];"
        : "=r"(r[0]), "=r"(r[1]), "=r"(r[2]), "=r"(r[3]) : "r"(addr));
}
__device__ __forceinline__ void mma_bf16(float* d, const uint32_t* a,
                                         uint32_t b0, uint32_t b1) {
    asm volatile(
        "mma.sync.aligned.m16n8k16.row.col.f32.bf16.bf16.f32 "
        "{%0,%1,%2,%3}, {%4,%5,%6,%7}, {%8,%9}, {%0,%1,%2,%3};"
        : "+f"(d[0]), "+f"(d[1]), "+f"(d[2]), "+f"(d[3])
        : "r"(a[0]), "r"(a[1]), "r"(a[2]), "r"(a[3]), "r"(b0), "r"(b1));
}
#define CP16(dst, src) asm volatile("cp.async.cg.shared.global [%0], [%1], 16;" :: "r"(dst), "l"(src))
#define CP_COMMIT()    asm volatile("cp.async.commit_group;" ::: "memory")
#define CP_WAIT(n)     asm volatile("cp.async.wait_group %0;" :: "n"(n) : "memory")

__device__ __forceinline__ void split1(float x, __nv_bfloat16& h, __nv_bfloat16& l) {
    h = __float2bfloat16(x);
    l = __float2bfloat16(x - __bfloat162float(h));
}

// ---------------------------------------------------------------------------
// Kernel 1: LayerNorm + projections -> bf16 hi/lo, layout [i*32+h][n]
// ---------------------------------------------------------------------------
__global__ __launch_bounds__(256) void ln_proj_kernel(
    const float* __restrict__ m, const float* __restrict__ mask,
    const float* __restrict__ gamma, const float* __restrict__ beta,
    const float* __restrict__ Wa, const float* __restrict__ ba,
    const float* __restrict__ Wb, const float* __restrict__ bb)
{
    extern __shared__ float sm1[];
    float* sWa  = sm1;
    float* sWb  = sWa + 8192;
    float* xs   = sWb + 8192;
    float* sred = xs + 256;
    float* scr  = sred + 256;
    __nv_bfloat16* sStage = (__nv_bfloat16*)(scr + 16);

    const int tid = threadIdx.x;
    for (int l = tid; l < 8192; l += 256) { sWa[l] = Wa[l]; sWb[l] = Wb[l]; }
    __syncthreads();

    const float gam = gamma[tid];
    const float bet = beta[tid];

    const int outp = tid & 63;
    const int part = tid >> 6;
    const int h    = outp & 31;
    const float* W = (outp < 32) ? sWa : sWb;

    const int nb = blockIdx.x >> 7;
    const int ib = blockIdx.x & 127;
    const int n0 = nb * 16;
    const int i0 = ib * 2;

    for (int rr = 0; rr < 32; rr++) {
        const int n_loc = rr & 15;
        const int i_loc = rr >> 4;
        const int row = (n0 + n_loc) * LL + (i0 + i_loc);

        const float xv = m[row * CM + tid];
        float a = xv, b = xv * xv;
#pragma unroll
        for (int o = 16; o > 0; o >>= 1) {
            a += __shfl_xor_sync(0xffffffffu, a, o);
            b += __shfl_xor_sync(0xffffffffu, b, o);
        }
        if ((tid & 31) == 0) { scr[tid >> 5] = a; scr[8 + (tid >> 5)] = b; }
        __syncthreads();
        if (tid < 32) {
            float x = (tid < 8) ? scr[tid] : 0.f;
            float y = (tid < 8) ? scr[8 + tid] : 0.f;
#pragma unroll
            for (int o = 4; o > 0; o >>= 1) {
                x += __shfl_xor_sync(0xffffffffu, x, o);
                y += __shfl_xor_sync(0xffffffffu, y, o);
            }
            if (tid == 0) { scr[0] = x; scr[8] = y; }
        }
        __syncthreads();
        const float mean = scr[0] * (1.f / 256.f);
        const float msq  = scr[8] * (1.f / 256.f);
        __syncthreads();
        const float var = msq - mean * mean;

        xs[tid] = (xv - mean) * rsqrtf(var + 1e-5f) * gam + bet;
        __syncthreads();

        float s = 0.f;
#pragma unroll
        for (int kk = 0; kk < 64; kk++) {
            const int k = part * 64 + kk;
            s += xs[k] * W[k * 32 + h];
        }
        sred[tid] = s;
        __syncthreads();

        if (tid < 64) {
            float tot = sred[tid] + sred[tid + 64] + sred[tid + 128] + sred[tid + 192];
            const float mk = mask[row];
            const int sidx = (i_loc * 32 + h) * 16 + n_loc;
            __nv_bfloat16 hi, lo;
            if (tid < 32) {
                split1((tot + ba[h]) * mk, hi, lo);
                sStage[0 * 1024 + sidx] = hi;
                sStage[1 * 1024 + sidx] = lo;
            } else {
                split1((tot + bb[h]) * mk, hi, lo);
                sStage[2 * 1024 + sidx] = hi;
                sStage[3 * 1024 + sidx] = lo;
            }
        }
        __syncthreads();
    }

#pragma unroll
    for (int v = 0; v < 2; v++) {
        const int fidx = v * 256 + tid;
        const int arr  = fidx >> 7;
        const int rem  = fidx & 127;
        const int il   = rem >> 6;
        const int hh   = (rem >> 1) & 31;
        const int half = rem & 1;
        const uint4 val = *reinterpret_cast<const uint4*>(
            sStage + arr * 1024 + (il * 32 + hh) * 16 + half * 8);
        __nv_bfloat16* gdst = (arr == 0) ? g_Ah : (arr == 1) ? g_Al : (arr == 2) ? g_Bh : g_Bl;
        reinterpret_cast<uint4*>(gdst)[((i0 + il) * 32 + hh) * 16 + nb * 2 + half] = val;
    }
}

// ---------------------------------------------------------------------------
// Prep: pair mask table + Wo^T bf16 split
// ---------------------------------------------------------------------------
__global__ __launch_bounds__(256) void prep_kernel(
    const float* __restrict__ mask, const float* __restrict__ Wo)
{
    if (blockIdx.x < 256) {
        const int i = blockIdx.x, j = threadIdx.x;
        float s = 0.f;
        for (int n = 0; n < NN; n++) s += mask[n * LL + i] * mask[n * LL + j];
        g_pm[i * LL + j] = s;
    } else {
        const int b = blockIdx.x - 256;
#pragma unroll
        for (int v = 0; v < 8; v++) {
            const int e = b * 2048 + v * 256 + threadIdx.x;
            const float val = Wo[e];
            const int k = e >> 7, z = e & 127;
            __nv_bfloat16 hi, lo;
            split1(val, hi, lo);
            g_Woh[z * 1024 + k] = hi;
            g_Wol[z * 1024 + k] = lo;
        }
    }
}

// ---------------------------------------------------------------------------
// Fused kernel: per CTA (bm,bn): O tile 128x128 (16 pairs) in regs,
// split to SMEM bf16 hi/lo, then Z = O @ Wo^T with Wo streamed (3-stage).
//
// SMEM map (bytes):
//   [0, 139264)      phase A: A/B tiles (4 bufs x 128 rows x 272)
//                    phase B: Wo stages (3 x 2 bufs x 128 rows x 144 = 110592)
//   [139264, 205312) O tile bf16: hi 16 x 2064, lo 16 x 2064
//   [205312, 221696) K-split reduction buffer (4096 fp32)
//   [221696, 221760) pair-mask inv (16 fp32)
// ---------------------------------------------------------------------------
#define FA_BUF   34816
#define FW_STAGE 36864
#define FW_BUF   18432
#define OFFO     139264
#define OFFOL    (OFFO + 33024)
#define OFFRED   205312
#define OFFPM    221696
#define F_SMEM   221760

__device__ __forceinline__ void load_wo_chunk(uint32_t sb, int st, int ck, int tid)
{
#pragma unroll
    for (int v = 0; v < 4; v++) {
        const int idx = v * 512 + tid;          // 0..2047
        const int buf = idx >> 10;
        const int rem = idx & 1023;
        const int row = rem >> 3, q = rem & 7;
        const __nv_bfloat16* src = (buf ? g_Wol : g_Woh) + (size_t)row * 1024 + ck * 64 + q * 8;
        CP16(sb + st * FW_STAGE + buf * FW_BUF + row * 144 + q * 16, src);
    }
    CP_COMMIT();
}

__global__ __launch_bounds__(512) void fused_kernel(
    const float* __restrict__ bo, float* __restrict__ out)
{
    extern __shared__ char smem[];
    const uint32_t sb = smem_u32(smem);
    const int tid  = threadIdx.x;
    const int lane = tid & 31;
    const int wid  = tid >> 5;
    const int bm = blockIdx.y, bn = blockIdx.x;
    const int i0 = bm * 4, j0 = bn * 4;

    // ============================ Phase A ============================
    // load A,B tiles (2 cp.async groups by k-half)
#pragma unroll
    for (int kh = 0; kh < 2; kh++) {
#pragma unroll
        for (int v = 0; v < 8; v++) {
            const int idx = v * 512 + tid;
            const int buf = idx >> 10;
            const int rem = idx & 1023;
            const int row = rem >> 3, q = rem & 7;
            const int grow = ((buf < 2) ? bm : bn) * 128 + row;
            const __nv_bfloat16* src = (buf == 0) ? g_Ah : (buf == 1) ? g_Al
                                     : (buf == 2) ? g_Bh : g_Bl;
            CP16(sb + buf * FA_BUF + row * 272 + kh * 128 + q * 16,
                 src + (size_t)grow * 128 + kh * 64 + q * 8);
        }
        CP_COMMIT();
    }

    const int wm = wid >> 2, wn = wid & 3;
    float acc[2][4][4];
#pragma unroll
    for (int fm = 0; fm < 2; fm++)
#pragma unroll
        for (int fn = 0; fn < 4; fn++)
#pragma unroll
            for (int e = 0; e < 4; e++) acc[fm][fn][e] = 0.f;

    const uint32_t rofsA = (uint32_t)((lane & 15) * 272 + (lane >> 4) * 16);
    const uint32_t aAh = sb + 0 * FA_BUF + wm * 32 * 272 + rofsA;
    const uint32_t aAl = sb + 1 * FA_BUF + wm * 32 * 272 + rofsA;
    const uint32_t aBh = sb + 2 * FA_BUF + wn * 32 * 272 + rofsA;
    const uint32_t aBl = sb + 3 * FA_BUF + wn * 32 * 272 + rofsA;

    CP_WAIT(1);
    __syncthreads();

#pragma unroll
    for (int ks = 0; ks < 8; ks++) {
        if (ks == 4) { CP_WAIT(0); __syncthreads(); }
        uint32_t A_h[2][4], A_l[2][4], B_h[2][4], B_l[2][4];
        ldsm4(A_h[0], aAh + ks * 32);
        ldsm4(A_h[1], aAh + 16 * 272 + ks * 32);
        ldsm4(A_l[0], aAl + ks * 32);
        ldsm4(A_l[1], aAl + 16 * 272 + ks * 32);
        ldsm4(B_h[0], aBh + ks * 32);
        ldsm4(B_h[1], aBh + 16 * 272 + ks * 32);
        ldsm4(B_l[0], aBl + ks * 32);
        ldsm4(B_l[1], aBl + 16 * 272 + ks * 32);
#pragma unroll
        for (int fm = 0; fm < 2; fm++)
#pragma unroll
            for (int fn = 0; fn < 4; fn++) {
                const uint32_t bh0 = B_h[fn >> 1][fn & 1];
                const uint32_t bh1 = B_h[fn >> 1][(fn & 1) + 2];
                const uint32_t bl0 = B_l[fn >> 1][fn & 1];
                const uint32_t bl1 = B_l[fn >> 1][(fn & 1) + 2];
                mma_bf16(acc[fm][fn], A_h[fm], bh0, bh1);
                mma_bf16(acc[fm][fn], A_h[fm], bl0, bl1);
                mma_bf16(acc[fm][fn], A_l[fm], bh0, bh1);
            }
    }

    __syncthreads();   // everyone done reading A/B smem

    // prefetch first two Wo chunks into the (now free) A/B region
    load_wo_chunk(sb, 0, 0, tid);
    load_wo_chunk(sb, 1, 1, tid);

    // spill O tile to smem as bf16 hi/lo, [pair p = wid][k = c*32+d], pitch 2064
    {
        char* oh = smem + OFFO  + wid * 2064;
        char* ol = smem + OFFOL + wid * 2064;
#pragma unroll
        for (int fm = 0; fm < 2; fm++)
#pragma unroll
            for (int fn = 0; fn < 4; fn++)
#pragma unroll
                for (int half = 0; half < 2; half++) {
                    const int c = (lane >> 2) + half * 8 + fm * 16;
                    const int k = c * 32 + (lane & 3) * 2 + fn * 8;
                    __nv_bfloat162 h2, l2;
                    split1(acc[fm][fn][half * 2 + 0], h2.x, l2.x);
                    split1(acc[fm][fn][half * 2 + 1], h2.y, l2.y);
                    *reinterpret_cast<__nv_bfloat162*>(oh + 2 * k) = h2;
                    *reinterpret_cast<__nv_bfloat162*>(ol + 2 * k) = l2;
                }
    }
    if (tid < 16) {
        const int ii = i0 + (tid >> 2), jj = j0 + (tid & 3);
        *reinterpret_cast<float*>(smem + OFFPM + tid * 4) =
            1.f / (g_pm[ii * LL + jj] + 1e-8f);
    }
    __syncthreads();

    // ============================ Phase B ============================
    // Z[16 pairs][128 z] = O @ Wo^T, K=1024 in 16 chunks of 64.
    // warp: wn2 = wid&7 (z slice of 16), kc = wid>>3 (k-split of 2)
    const int wn2 = wid & 7;
    const int kc  = wid >> 3;

    float acc2[2][4];
#pragma unroll
    for (int fn = 0; fn < 2; fn++)
#pragma unroll
        for (int e = 0; e < 4; e++) acc2[fn][e] = 0.f;

    const uint32_t aOh = sb + OFFO  + (uint32_t)((lane & 15) * 2064 + (lane >> 4) * 16);
    const uint32_t aOl = aOh + 33024;
    const uint32_t rofsW = (uint32_t)(wn2 * 16 * 144 + (lane & 15) * 144 + (lane >> 4) * 16);

    for (int ck = 0; ck < 16; ck++) {
        const int st = ck % 3;
        if (ck < 15) CP_WAIT(1); else CP_WAIT(0);
        __syncthreads();
        if (ck + 2 < 16) load_wo_chunk(sb, (ck + 2) % 3, ck + 2, tid);

        const uint32_t bWh = sb + st * FW_STAGE + rofsW;
        const uint32_t bWl = bWh + FW_BUF;

#pragma unroll
        for (int ks2 = 0; ks2 < 2; ks2++) {
            const int ks = kc * 2 + ks2;                 // 0..3 within chunk
            uint32_t A_h[4], A_l[4], B_h[4], B_l[4];
            ldsm4(A_h, aOh + ck * 128 + ks * 32);
            ldsm4(A_l, aOl + ck * 128 + ks * 32);
            ldsm4(B_h, bWh + ks * 32);
            ldsm4(B_l, bWl + ks * 32);
#pragma unroll
            for (int fn = 0; fn < 2; fn++) {
                const uint32_t bh0 = B_h[fn], bh1 = B_h[fn + 2];
                const uint32_t bl0 = B_l[fn], bl1 = B_l[fn + 2];
                mma_bf16(acc2[fn], A_h, bh0, bh1);
                mma_bf16(acc2[fn], A_h, bl0, bl1);
                mma_bf16(acc2[fn], A_l, bh0, bh1);
            }
        }
    }

    // K-split reduction: kc=1 warps dump partials, kc=0 warps combine + store
    float* red = reinterpret_cast<float*>(smem + OFFRED);
    if (kc == 1) {
#pragma unroll
        for (int fn = 0; fn < 2; fn++)
#pragma unroll
            for (int e = 0; e < 4; e++) {
                const int p  = (lane >> 2) + (e >> 1) * 8;
                const int zl = fn * 8 + (lane & 3) * 2 + (e & 1);
                red[wn2 * 256 + p * 16 + zl] = acc2[fn][e];
            }
    }
    __syncthreads();
    if (kc == 0) {
        const float* pmv = reinterpret_cast<const float*>(smem + OFFPM);
#pragma unroll
        for (int fn = 0; fn < 2; fn++)
#pragma unroll
            for (int e = 0; e < 4; e++) {
                const int p  = (lane >> 2) + (e >> 1) * 8;
                const int zl = fn * 8 + (lane & 3) * 2 + (e & 1);
                acc2[fn][e] += red[wn2 * 256 + p * 16 + zl];
            }
#pragma unroll
        for (int fn = 0; fn < 2; fn++)
#pragma unroll
            for (int prow = 0; prow < 2; prow++) {
                const int p = (lane >> 2) + prow * 8;
                const int ii = i0 + (p >> 2), jj = j0 + (p & 3);
                const float inv = pmv[p];
                const int z = wn2 * 16 + fn * 8 + (lane & 3) * 2;
                float2 res;
                res.x = acc2[fn][prow * 2 + 0] * inv + bo[z];
                res.y = acc2[fn][prow * 2 + 1] * inv + bo[z + 1];
                *reinterpret_cast<float2*>(out + (size_t)(ii * LL + jj) * CZ + z) = res;
            }
    }
}

// ---------------------------------------------------------------------------
extern "C" void kernel_launch(void* const* d_in, const int* in_sizes, int n_in,
                              void* d_out, int out_size)
{
    const float* m     = (const float*)d_in[0];
    const float* mask  = (const float*)d_in[1];
    const float* gamma = (const float*)d_in[2];
    const float* beta  = (const float*)d_in[3];
    const float* Wa    = (const float*)d_in[4];
    const float* ba    = (const float*)d_in[5];
    const float* Wb    = (const float*)d_in[6];
    const float* bb    = (const float*)d_in[7];
    const float* Wo    = (const float*)d_in[8];
    const float* bo    = (const float*)d_in[9];
    float* out = (float*)d_out;

    const int smem1 = 16912 * 4 + 4096 * 2;
    cudaFuncSetAttribute(ln_proj_kernel, cudaFuncAttributeMaxDynamicSharedMemorySize, smem1);
    cudaFuncSetAttribute(fused_kernel,   cudaFuncAttributeMaxDynamicSharedMemorySize, F_SMEM);

    ln_proj_kernel<<<1024, 256, smem1>>>(m, mask, gamma, beta, Wa, ba, Wb, bb);
    prep_kernel<<<320, 256>>>(mask, Wo);
    fused_kernel<<<dim3(64, 64), 512, F_SMEM>>>(bo, out);
}

// round 9
// speedup vs baseline: 1.3801x; 1.2238x over previous
#include <cuda_runtime.h>
#include <cuda_bf16.h>
#include <cstdint>

#define NN 128
#define LL 256
#define CM 256
#define CH 32
#define CZ 128
#define RTOT 8192   // LL*CH

// ---------------- global scratch ----------------
__device__ __align__(16) __nv_bfloat16 g_Xh[(size_t)32768 * 256];  // LN(x) hi
__device__ __align__(16) __nv_bfloat16 g_Xl[(size_t)32768 * 256];  // LN(x) lo
__device__ __align__(16) __nv_bfloat16 g_Wth[64 * 256];   // [o][k]  ([Wa|Wb]^T)
__device__ __align__(16) __nv_bfloat16 g_Wtl[64 * 256];
__device__ __align__(16) __nv_bfloat16 g_Ah[RTOT * NN];   // [r=i*32+h][n]
__device__ __align__(16) __nv_bfloat16 g_Al[RTOT * NN];
__device__ __align__(16) __nv_bfloat16 g_Bh[RTOT * NN];
__device__ __align__(16) __nv_bfloat16 g_Bl[RTOT * NN];
__device__ __align__(16) __nv_bfloat16 g_Woh[CZ * 1024];  // [z][k] (Wo^T)
__device__ __align__(16) __nv_bfloat16 g_Wol[CZ * 1024];
__device__ float g_pm[LL * LL];

// ---------------- helpers ----------------
__device__ __forceinline__ uint32_t smem_u32(const void* p) {
    uint32_t a;
    asm("{ .reg .u64 t; cvta.to.shared.u64 t, %1; cvt.u32.u64 %0, t; }" : "=r"(a) : "l"(p));
    return a;
}
__device__ __forceinline__ void ldsm4(uint32_t* r, uint32_t addr) {
    asm volatile("ldmatrix.sync.aligned.m8n8.x4.shared.b16 {%0,%1,%2,%3}, [%4];"
        : "=r"(r[0]), "=r"(r[1]), "=r"(r[2]), "=r"(r[3]) : "r"(addr));
}
__device__ __forceinline__ void mma_bf16(float* d, const uint32_t* a,
                                         uint32_t b0, uint32_t b1) {
    asm volatile(
        "mma.sync.aligned.m16n8k16.row.col.f32.bf16.bf16.f32 "
        "{%0,%1,%2,%3}, {%4,%5,%6,%7}, {%8,%9}, {%0,%1,%2,%3};"
        : "+f"(d[0]), "+f"(d[1]), "+f"(d[2]), "+f"(d[3])
        : "r"(a[0]), "r"(a[1]), "r"(a[2]), "r"(a[3]), "r"(b0), "r"(b1));
}
#define CP16(dst, src) asm volatile("cp.async.cg.shared.global [%0], [%1], 16;" :: "r"(dst), "l"(src))
#define CP_COMMIT()    asm volatile("cp.async.commit_group;" ::: "memory")
#define CP_WAIT(n)     asm volatile("cp.async.wait_group %0;" :: "n"(n) : "memory")

__device__ __forceinline__ void split1(float x, __nv_bfloat16& h, __nv_bfloat16& l) {
    h = __float2bfloat16(x);
    l = __float2bfloat16(x - __bfloat162float(h));
}

// ---------------------------------------------------------------------------
// ln_kernel: warp-per-row LayerNorm, shuffle-only, no smem, no block syncs.
// Emits x hi/lo bf16 in [row][c] layout.
// ---------------------------------------------------------------------------
__global__ __launch_bounds__(256) void ln_kernel(
    const float* __restrict__ m, const float* __restrict__ gamma,
    const float* __restrict__ beta)
{
    const int row  = blockIdx.x * 8 + (threadIdx.x >> 5);
    const int lane = threadIdx.x & 31;
    const size_t base = (size_t)row * 256 + lane * 8;

    const float4 v0 = *reinterpret_cast<const float4*>(m + base);
    const float4 v1 = *reinterpret_cast<const float4*>(m + base + 4);
    float x[8] = {v0.x, v0.y, v0.z, v0.w, v1.x, v1.y, v1.z, v1.w};

    float s = 0.f, q = 0.f;
#pragma unroll
    for (int c = 0; c < 8; c++) { s += x[c]; q += x[c] * x[c]; }
#pragma unroll
    for (int o = 16; o > 0; o >>= 1) {
        s += __shfl_xor_sync(0xffffffffu, s, o);
        q += __shfl_xor_sync(0xffffffffu, q, o);
    }
    const float mean = s * (1.f / 256.f);
    const float var  = q * (1.f / 256.f) - mean * mean;
    const float rstd = rsqrtf(var + 1e-5f);

    const float4 g0 = *reinterpret_cast<const float4*>(gamma + lane * 8);
    const float4 g1 = *reinterpret_cast<const float4*>(gamma + lane * 8 + 4);
    const float4 b0 = *reinterpret_cast<const float4*>(beta + lane * 8);
    const float4 b1 = *reinterpret_cast<const float4*>(beta + lane * 8 + 4);
    const float gm[8] = {g0.x, g0.y, g0.z, g0.w, g1.x, g1.y, g1.z, g1.w};
    const float bt[8] = {b0.x, b0.y, b0.z, b0.w, b1.x, b1.y, b1.z, b1.w};

    __nv_bfloat16 hb[8], lb[8];
#pragma unroll
    for (int c = 0; c < 8; c++) {
        const float y = (x[c] - mean) * rstd * gm[c] + bt[c];
        split1(y, hb[c], lb[c]);
    }
    *reinterpret_cast<uint4*>(g_Xh + base) = *reinterpret_cast<const uint4*>(hb);
    *reinterpret_cast<uint4*>(g_Xl + base) = *reinterpret_cast<const uint4*>(lb);
}

// ---------------------------------------------------------------------------
// Prep: pair-mask table + Wo^T bf16 split + [Wa|Wb]^T bf16 split
// ---------------------------------------------------------------------------
__global__ __launch_bounds__(256) void prep_kernel(
    const float* __restrict__ mask, const float* __restrict__ Wo,
    const float* __restrict__ Wa, const float* __restrict__ Wb)
{
    const int t = threadIdx.x;
    if (blockIdx.x < 256) {
        const int i = blockIdx.x, j = t;
        float s = 0.f;
        for (int n = 0; n < NN; n++) s += mask[n * LL + i] * mask[n * LL + j];
        g_pm[i * LL + j] = s;
    } else if (blockIdx.x < 320) {
        const int b = blockIdx.x - 256;
#pragma unroll
        for (int v = 0; v < 8; v++) {
            const int e = b * 2048 + v * 256 + t;
            const float val = Wo[e];
            const int k = e >> 7, z = e & 127;
            __nv_bfloat16 hi, lo;
            split1(val, hi, lo);
            g_Woh[z * 1024 + k] = hi;
            g_Wol[z * 1024 + k] = lo;
        }
    } else {
        const int idx = (blockIdx.x - 320) * 256 + t;   // 0..16383
        const int o = idx >> 8, k = idx & 255;
        const float val = (o < 32) ? Wa[k * 32 + o] : Wb[k * 32 + (o - 32)];
        __nv_bfloat16 hi, lo;
        split1(val, hi, lo);
        g_Wth[o * 256 + k] = hi;
        g_Wtl[o * 256 + k] = lo;
    }
}

// ---------------------------------------------------------------------------
// proj_kernel: a|b = X @ [Wa|Wb] (+bias)*mask, via bf16-split mma.
// CTA = one i (256 CTAs): M = 128 n-rows, N = 64 outs, K = 256.
// Epilogue stores split a/b in [i*32+h][n] layout (fused kernel's input).
// SMEM: Xh 0 | Xl 67584 | Wh 135168 | Wl 168960 | mask 202752 ; sOut reuses 0
// ---------------------------------------------------------------------------
#define P_XH   0
#define P_XL   67584
#define P_WH   135168
#define P_WL   168960
#define P_MASK 202752
#define P_SMEM 203264

__global__ __launch_bounds__(512) void proj_kernel(
    const float* __restrict__ mask,
    const float* __restrict__ ba, const float* __restrict__ bb)
{
    extern __shared__ char smem[];
    const uint32_t sb = smem_u32(smem);
    const int tid  = threadIdx.x;
    const int lane = tid & 31;
    const int wid  = tid >> 5;
    const int i = blockIdx.x;

    // X tiles: 128 rows (n) x 256 k, hi+lo
#pragma unroll
    for (int v = 0; v < 16; v++) {
        const int idx = v * 512 + tid;          // 0..8191
        const int buf = idx >> 12;
        const int rem = idx & 4095;
        const int rown = rem >> 5, q = rem & 31;
        const __nv_bfloat16* src = (buf ? g_Xl : g_Xh) +
            (size_t)(rown * 256 + i) * 256 + q * 8;
        CP16(sb + (buf ? P_XL : P_XH) + rown * 528 + q * 16, src);
    }
    // W tiles: 64 rows (o) x 256 k, hi+lo
#pragma unroll
    for (int v = 0; v < 8; v++) {
        const int idx = v * 512 + tid;          // 0..4095
        const int buf = idx >> 11;
        const int rem = idx & 2047;
        const int rowo = rem >> 5, q = rem & 31;
        const __nv_bfloat16* src = (buf ? g_Wtl : g_Wth) + rowo * 256 + q * 8;
        CP16(sb + (buf ? P_WL : P_WH) + rowo * 528 + q * 16, src);
    }
    CP_COMMIT();

    if (tid < 128)
        *reinterpret_cast<float*>(smem + P_MASK + tid * 4) = mask[tid * LL + i];

    CP_WAIT(0);
    __syncthreads();

    const int wm = wid >> 2, wn = wid & 3;   // wm: 32 n-rows, wn: 16 outs
    float acc[2][2][4];
#pragma unroll
    for (int fm = 0; fm < 2; fm++)
#pragma unroll
        for (int fn = 0; fn < 2; fn++)
#pragma unroll
            for (int e = 0; e < 4; e++) acc[fm][fn][e] = 0.f;

    const uint32_t rofs = (uint32_t)((lane & 15) * 528 + (lane >> 4) * 16);
    const uint32_t aXh = sb + P_XH + wm * 32 * 528 + rofs;
    const uint32_t aXl = sb + P_XL + wm * 32 * 528 + rofs;
    const uint32_t aWh = sb + P_WH + wn * 16 * 528 + rofs;
    const uint32_t aWl = sb + P_WL + wn * 16 * 528 + rofs;

#pragma unroll
    for (int ks = 0; ks < 16; ks++) {
        uint32_t X_h[2][4], X_l[2][4], W_h[4], W_l[4];
        ldsm4(X_h[0], aXh + ks * 32);
        ldsm4(X_h[1], aXh + 16 * 528 + ks * 32);
        ldsm4(X_l[0], aXl + ks * 32);
        ldsm4(X_l[1], aXl + 16 * 528 + ks * 32);
        ldsm4(W_h, aWh + ks * 32);
        ldsm4(W_l, aWl + ks * 32);
#pragma unroll
        for (int fm = 0; fm < 2; fm++)
#pragma unroll
            for (int fn = 0; fn < 2; fn++) {
                const uint32_t bh0 = W_h[fn], bh1 = W_h[fn + 2];
                const uint32_t bl0 = W_l[fn], bl1 = W_l[fn + 2];
                mma_bf16(acc[fm][fn], X_h[fm], bh0, bh1);
                mma_bf16(acc[fm][fn], X_h[fm], bl0, bl1);
                mma_bf16(acc[fm][fn], X_l[fm], bh0, bh1);
            }
    }

    __syncthreads();   // done reading X/W smem -> reuse for sOut

    // stage (acc + bias) * mask into sOut[o][n], pitch 132 floats
    float* sOut = reinterpret_cast<float*>(smem);
    const float* sMask = reinterpret_cast<const float*>(smem + P_MASK);
#pragma unroll
    for (int fm = 0; fm < 2; fm++)
#pragma unroll
        for (int fn = 0; fn < 2; fn++)
#pragma unroll
            for (int e = 0; e < 4; e++) {
                const int n_loc = wm * 32 + fm * 16 + (lane >> 2) + (e >> 1) * 8;
                const int o     = wn * 16 + fn * 8 + (lane & 3) * 2 + (e & 1);
                const float bias = (o < 32) ? ba[o] : bb[o - 32];
                sOut[o * 132 + n_loc] = (acc[fm][fn][e] + bias) * sMask[n_loc];
            }
    __syncthreads();

    // write out: thread t -> o = t>>3, n chunk = (t&7)*16 (contiguous 32B x2)
    {
        const int o  = tid >> 3;
        const int n0 = (tid & 7) * 16;
        __nv_bfloat16 hb[16], lb[16];
#pragma unroll
        for (int c = 0; c < 16; c++)
            split1(sOut[o * 132 + n0 + c], hb[c], lb[c]);
        __nv_bfloat16* dh = ((o < 32) ? g_Ah : g_Bh) + (size_t)(i * 32 + (o & 31)) * 128 + n0;
        __nv_bfloat16* dl = ((o < 32) ? g_Al : g_Bl) + (size_t)(i * 32 + (o & 31)) * 128 + n0;
        reinterpret_cast<uint4*>(dh)[0] = reinterpret_cast<const uint4*>(hb)[0];
        reinterpret_cast<uint4*>(dh)[1] = reinterpret_cast<const uint4*>(hb)[1];
        reinterpret_cast<uint4*>(dl)[0] = reinterpret_cast<const uint4*>(lb)[0];
        reinterpret_cast<uint4*>(dl)[1] = reinterpret_cast<const uint4*>(lb)[1];
    }
}

// ---------------------------------------------------------------------------
// Fused kernel (unchanged from R8): O tile in regs -> smem bf16 -> @ Wo^T
// ---------------------------------------------------------------------------
#define FA_BUF   34816
#define FW_STAGE 36864
#define FW_BUF   18432
#define OFFO     139264
#define OFFOL    (OFFO + 33024)
#define OFFRED   205312
#define OFFPM    221696
#define F_SMEM   221760

__device__ __forceinline__ void load_wo_chunk(uint32_t sb, int st, int ck, int tid)
{
#pragma unroll
    for (int v = 0; v < 4; v++) {
        const int idx = v * 512 + tid;
        const int buf = idx >> 10;
        const int rem = idx & 1023;
        const int row = rem >> 3, q = rem & 7;
        const __nv_bfloat16* src = (buf ? g_Wol : g_Woh) + (size_t)row * 1024 + ck * 64 + q * 8;
        CP16(sb + st * FW_STAGE + buf * FW_BUF + row * 144 + q * 16, src);
    }
    CP_COMMIT();
}

__global__ __launch_bounds__(512) void fused_kernel(
    const float* __restrict__ bo, float* __restrict__ out)
{
    extern __shared__ char smem[];
    const uint32_t sb = smem_u32(smem);
    const int tid  = threadIdx.x;
    const int lane = tid & 31;
    const int wid  = tid >> 5;
    const int bm = blockIdx.y, bn = blockIdx.x;
    const int i0 = bm * 4, j0 = bn * 4;

#pragma unroll
    for (int kh = 0; kh < 2; kh++) {
#pragma unroll
        for (int v = 0; v < 8; v++) {
            const int idx = v * 512 + tid;
            const int buf = idx >> 10;
            const int rem = idx & 1023;
            const int row = rem >> 3, q = rem & 7;
            const int grow = ((buf < 2) ? bm : bn) * 128 + row;
            const __nv_bfloat16* src = (buf == 0) ? g_Ah : (buf == 1) ? g_Al
                                     : (buf == 2) ? g_Bh : g_Bl;
            CP16(sb + buf * FA_BUF + row * 272 + kh * 128 + q * 16,
                 src + (size_t)grow * 128 + kh * 64 + q * 8);
        }
        CP_COMMIT();
    }

    const int wm = wid >> 2, wn = wid & 3;
    float acc[2][4][4];
#pragma unroll
    for (int fm = 0; fm < 2; fm++)
#pragma unroll
        for (int fn = 0; fn < 4; fn++)
#pragma unroll
            for (int e = 0; e < 4; e++) acc[fm][fn][e] = 0.f;

    const uint32_t rofsA = (uint32_t)((lane & 15) * 272 + (lane >> 4) * 16);
    const uint32_t aAh = sb + 0 * FA_BUF + wm * 32 * 272 + rofsA;
    const uint32_t aAl = sb + 1 * FA_BUF + wm * 32 * 272 + rofsA;
    const uint32_t aBh = sb + 2 * FA_BUF + wn * 32 * 272 + rofsA;
    const uint32_t aBl = sb + 3 * FA_BUF + wn * 32 * 272 + rofsA;

    CP_WAIT(1);
    __syncthreads();

#pragma unroll
    for (int ks = 0; ks < 8; ks++) {
        if (ks == 4) { CP_WAIT(0); __syncthreads(); }
        uint32_t A_h[2][4], A_l[2][4], B_h[2][4], B_l[2][4];
        ldsm4(A_h[0], aAh + ks * 32);
        ldsm4(A_h[1], aAh + 16 * 272 + ks * 32);
        ldsm4(A_l[0], aAl + ks * 32);
        ldsm4(A_l[1], aAl + 16 * 272 + ks * 32);
        ldsm4(B_h[0], aBh + ks * 32);
        ldsm4(B_h[1], aBh + 16 * 272 + ks * 32);
        ldsm4(B_l[0], aBl + ks * 32);
        ldsm4(B_l[1], aBl + 16 * 272 + ks * 32);
#pragma unroll
        for (int fm = 0; fm < 2; fm++)
#pragma unroll
            for (int fn = 0; fn < 4; fn++) {
                const uint32_t bh0 = B_h[fn >> 1][fn & 1];
                const uint32_t bh1 = B_h[fn >> 1][(fn & 1) + 2];
                const uint32_t bl0 = B_l[fn >> 1][fn & 1];
                const uint32_t bl1 = B_l[fn >> 1][(fn & 1) + 2];
                mma_bf16(acc[fm][fn], A_h[fm], bh0, bh1);
                mma_bf16(acc[fm][fn], A_h[fm], bl0, bl1);
                mma_bf16(acc[fm][fn], A_l[fm], bh0, bh1);
            }
    }

    __syncthreads();

    load_wo_chunk(sb, 0, 0, tid);
    load_wo_chunk(sb, 1, 1, tid);

    {
        char* oh = smem + OFFO  + wid * 2064;
        char* ol = smem + OFFOL + wid * 2064;
#pragma unroll
        for (int fm = 0; fm < 2; fm++)
#pragma unroll
            for (int fn = 0; fn < 4; fn++)
#pragma unroll
                for (int half = 0; half < 2; half++) {
                    const int c = (lane >> 2) + half * 8 + fm * 16;
                    const int k = c * 32 + (lane & 3) * 2 + fn * 8;
                    __nv_bfloat162 h2, l2;
                    split1(acc[fm][fn][half * 2 + 0], h2.x, l2.x);
                    split1(acc[fm][fn][half * 2 + 1], h2.y, l2.y);
                    *reinterpret_cast<__nv_bfloat162*>(oh + 2 * k) = h2;
                    *reinterpret_cast<__nv_bfloat162*>(ol + 2 * k) = l2;
                }
    }
    if (tid < 16) {
        const int ii = i0 + (tid >> 2), jj = j0 + (tid & 3);
        *reinterpret_cast<float*>(smem + OFFPM + tid * 4) =
            1.f / (g_pm[ii * LL + jj] + 1e-8f);
    }
    __syncthreads();

    const int wn2 = wid & 7;
    const int kc  = wid >> 3;

    float acc2[2][4];
#pragma unroll
    for (int fn = 0; fn < 2; fn++)
#pragma unroll
        for (int e = 0; e < 4; e++) acc2[fn][e] = 0.f;

    const uint32_t aOh = sb + OFFO  + (uint32_t)((lane & 15) * 2064 + (lane >> 4) * 16);
    const uint32_t aOl = aOh + 33024;
    const uint32_t rofsW = (uint32_t)(wn2 * 16 * 144 + (lane & 15) * 144 + (lane >> 4) * 16);

    for (int ck = 0; ck < 16; ck++) {
        const int st = ck % 3;
        if (ck < 15) CP_WAIT(1); else CP_WAIT(0);
        __syncthreads();
        if (ck + 2 < 16) load_wo_chunk(sb, (ck + 2) % 3, ck + 2, tid);

        const uint32_t bWh = sb + st * FW_STAGE + rofsW;
        const uint32_t bWl = bWh + FW_BUF;

#pragma unroll
        for (int ks2 = 0; ks2 < 2; ks2++) {
            const int ks = kc * 2 + ks2;
            uint32_t A_h[4], A_l[4], B_h[4], B_l[4];
            ldsm4(A_h, aOh + ck * 128 + ks * 32);
            ldsm4(A_l, aOl + ck * 128 + ks * 32);
            ldsm4(B_h, bWh + ks * 32);
            ldsm4(B_l, bWl + ks * 32);
#pragma unroll
            for (int fn = 0; fn < 2; fn++) {
                const uint32_t bh0 = B_h[fn], bh1 = B_h[fn + 2];
                const uint32_t bl0 = B_l[fn], bl1 = B_l[fn + 2];
                mma_bf16(acc2[fn], A_h, bh0, bh1);
                mma_bf16(acc2[fn], A_h, bl0, bl1);
                mma_bf16(acc2[fn], A_l, bh0, bh1);
            }
        }
    }

    float* red = reinterpret_cast<float*>(smem + OFFRED);
    if (kc == 1) {
#pragma unroll
        for (int fn = 0; fn < 2; fn++)
#pragma unroll
            for (int e = 0; e < 4; e++) {
                const int p  = (lane >> 2) + (e >> 1) * 8;
                const int zl = fn * 8 + (lane & 3) * 2 + (e & 1);
                red[wn2 * 256 + p * 16 + zl] = acc2[fn][e];
            }
    }
    __syncthreads();
    if (kc == 0) {
        const float* pmv = reinterpret_cast<const float*>(smem + OFFPM);
#pragma unroll
        for (int fn = 0; fn < 2; fn++)
#pragma unroll
            for (int e = 0; e < 4; e++) {
                const int p  = (lane >> 2) + (e >> 1) * 8;
                const int zl = fn * 8 + (lane & 3) * 2 + (e & 1);
                acc2[fn][e] += red[wn2 * 256 + p * 16 + zl];
            }
#pragma unroll
        for (int fn = 0; fn < 2; fn++)
#pragma unroll
            for (int prow = 0; prow < 2; prow++) {
                const int p = (lane >> 2) + prow * 8;
                const int ii = i0 + (p >> 2), jj = j0 + (p & 3);
                const float inv = pmv[p];
                const int z = wn2 * 16 + fn * 8 + (lane & 3) * 2;
                float2 res;
                res.x = acc2[fn][prow * 2 + 0] * inv + bo[z];
                res.y = acc2[fn][prow * 2 + 1] * inv + bo[z + 1];
                *reinterpret_cast<float2*>(out + (size_t)(ii * LL + jj) * CZ + z) = res;
            }
    }
}

// ---------------------------------------------------------------------------
extern "C" void kernel_launch(void* const* d_in, const int* in_sizes, int n_in,
                              void* d_out, int out_size)
{
    const float* m     = (const float*)d_in[0];
    const float* mask  = (const float*)d_in[1];
    const float* gamma = (const float*)d_in[2];
    const float* beta  = (const float*)d_in[3];
    const float* Wa    = (const float*)d_in[4];
    const float* ba    = (const float*)d_in[5];
    const float* Wb    = (const float*)d_in[6];
    const float* bb    = (const float*)d_in[7];
    const float* Wo    = (const float*)d_in[8];
    const float* bo    = (const float*)d_in[9];
    float* out = (float*)d_out;

    cudaFuncSetAttribute(proj_kernel,  cudaFuncAttributeMaxDynamicSharedMemorySize, P_SMEM);
    cudaFuncSetAttribute(fused_kernel, cudaFuncAttributeMaxDynamicSharedMemorySize, F_SMEM);

    ln_kernel<<<4096, 256>>>(m, gamma, beta);
    prep_kernel<<<384, 256>>>(mask, Wo, Wa, Wb);
    proj_kernel<<<256, 512, P_SMEM>>>(mask, ba, bb);
    fused_kernel<<<dim3(64, 64), 512, F_SMEM>>>(bo, out);
}

// round 10
// speedup vs baseline: 1.3833x; 1.0024x over previous
#include <cuda_runtime.h>
#include <cuda_bf16.h>
#include <cstdint>

#define NN 128
#define LL 256
#define CM 256
#define CH 32
#define CZ 128
#define RTOT 8192   // LL*CH

// ---------------- global scratch ----------------
__device__ __align__(16) __nv_bfloat16 g_Xh[(size_t)32768 * 256];  // LN(x) hi
__device__ __align__(16) __nv_bfloat16 g_Xl[(size_t)32768 * 256];  // LN(x) lo
__device__ __align__(16) __nv_bfloat16 g_Wth[64 * 256];   // [o][k]  ([Wa|Wb]^T)
__device__ __align__(16) __nv_bfloat16 g_Wtl[64 * 256];
__device__ __align__(16) __nv_bfloat16 g_Ah[RTOT * NN];   // [r=i*32+h][n]
__device__ __align__(16) __nv_bfloat16 g_Al[RTOT * NN];
__device__ __align__(16) __nv_bfloat16 g_Bh[RTOT * NN];
__device__ __align__(16) __nv_bfloat16 g_Bl[RTOT * NN];
__device__ __align__(16) __nv_bfloat16 g_Woh[CZ * 1024];  // [z][k] (Wo^T)
__device__ __align__(16) __nv_bfloat16 g_Wol[CZ * 1024];
__device__ float g_pm[LL * LL];

// ---------------- helpers ----------------
__device__ __forceinline__ uint32_t smem_u32(const void* p) {
    uint32_t a;
    asm("{ .reg .u64 t; cvta.to.shared.u64 t, %1; cvt.u32.u64 %0, t; }" : "=r"(a) : "l"(p));
    return a;
}
__device__ __forceinline__ void ldsm4(uint32_t* r, uint32_t addr) {
    asm volatile("ldmatrix.sync.aligned.m8n8.x4.shared.b16 {%0,%1,%2,%3}, [%4];"
        : "=r"(r[0]), "=r"(r[1]), "=r"(r[2]), "=r"(r[3]) : "r"(addr));
}
__device__ __forceinline__ void mma_bf16(float* d, const uint32_t* a,
                                         uint32_t b0, uint32_t b1) {
    asm volatile(
        "mma.sync.aligned.m16n8k16.row.col.f32.bf16.bf16.f32 "
        "{%0,%1,%2,%3}, {%4,%5,%6,%7}, {%8,%9}, {%0,%1,%2,%3};"
        : "+f"(d[0]), "+f"(d[1]), "+f"(d[2]), "+f"(d[3])
        : "r"(a[0]), "r"(a[1]), "r"(a[2]), "r"(a[3]), "r"(b0), "r"(b1));
}
#define CP16(dst, src) asm volatile("cp.async.cg.shared.global [%0], [%1], 16;" :: "r"(dst), "l"(src))
#define CP_COMMIT()    asm volatile("cp.async.commit_group;" ::: "memory")
#define CP_WAIT(n)     asm volatile("cp.async.wait_group %0;" :: "n"(n) : "memory")

__device__ __forceinline__ void split1(float x, __nv_bfloat16& h, __nv_bfloat16& l) {
    h = __float2bfloat16(x);
    l = __float2bfloat16(x - __bfloat162float(h));
}

// ---------------------------------------------------------------------------
// ln_kernel: warp-per-row LayerNorm (unchanged from R9)
// ---------------------------------------------------------------------------
__global__ __launch_bounds__(256) void ln_kernel(
    const float* __restrict__ m, const float* __restrict__ gamma,
    const float* __restrict__ beta)
{
    const int row  = blockIdx.x * 8 + (threadIdx.x >> 5);
    const int lane = threadIdx.x & 31;
    const size_t base = (size_t)row * 256 + lane * 8;

    const float4 v0 = *reinterpret_cast<const float4*>(m + base);
    const float4 v1 = *reinterpret_cast<const float4*>(m + base + 4);
    float x[8] = {v0.x, v0.y, v0.z, v0.w, v1.x, v1.y, v1.z, v1.w};

    float s = 0.f, q = 0.f;
#pragma unroll
    for (int c = 0; c < 8; c++) { s += x[c]; q += x[c] * x[c]; }
#pragma unroll
    for (int o = 16; o > 0; o >>= 1) {
        s += __shfl_xor_sync(0xffffffffu, s, o);
        q += __shfl_xor_sync(0xffffffffu, q, o);
    }
    const float mean = s * (1.f / 256.f);
    const float var  = q * (1.f / 256.f) - mean * mean;
    const float rstd = rsqrtf(var + 1e-5f);

    const float4 g0 = *reinterpret_cast<const float4*>(gamma + lane * 8);
    const float4 g1 = *reinterpret_cast<const float4*>(gamma + lane * 8 + 4);
    const float4 b0 = *reinterpret_cast<const float4*>(beta + lane * 8);
    const float4 b1 = *reinterpret_cast<const float4*>(beta + lane * 8 + 4);
    const float gm[8] = {g0.x, g0.y, g0.z, g0.w, g1.x, g1.y, g1.z, g1.w};
    const float bt[8] = {b0.x, b0.y, b0.z, b0.w, b1.x, b1.y, b1.z, b1.w};

    __nv_bfloat16 hb[8], lb[8];
#pragma unroll
    for (int c = 0; c < 8; c++) {
        const float y = (x[c] - mean) * rstd * gm[c] + bt[c];
        split1(y, hb[c], lb[c]);
    }
    *reinterpret_cast<uint4*>(g_Xh + base) = *reinterpret_cast<const uint4*>(hb);
    *reinterpret_cast<uint4*>(g_Xl + base) = *reinterpret_cast<const uint4*>(lb);
}

// ---------------------------------------------------------------------------
// Prep: pair-mask table + Wo^T bf16 split + [Wa|Wb]^T bf16 split (unchanged)
// ---------------------------------------------------------------------------
__global__ __launch_bounds__(256) void prep_kernel(
    const float* __restrict__ mask, const float* __restrict__ Wo,
    const float* __restrict__ Wa, const float* __restrict__ Wb)
{
    const int t = threadIdx.x;
    if (blockIdx.x < 256) {
        const int i = blockIdx.x, j = t;
        float s = 0.f;
        for (int n = 0; n < NN; n++) s += mask[n * LL + i] * mask[n * LL + j];
        g_pm[i * LL + j] = s;
    } else if (blockIdx.x < 320) {
        const int b = blockIdx.x - 256;
#pragma unroll
        for (int v = 0; v < 8; v++) {
            const int e = b * 2048 + v * 256 + t;
            const float val = Wo[e];
            const int k = e >> 7, z = e & 127;
            __nv_bfloat16 hi, lo;
            split1(val, hi, lo);
            g_Woh[z * 1024 + k] = hi;
            g_Wol[z * 1024 + k] = lo;
        }
    } else {
        const int idx = (blockIdx.x - 320) * 256 + t;
        const int o = idx >> 8, k = idx & 255;
        const float val = (o < 32) ? Wa[k * 32 + o] : Wb[k * 32 + (o - 32)];
        __nv_bfloat16 hi, lo;
        split1(val, hi, lo);
        g_Wth[o * 256 + k] = hi;
        g_Wtl[o * 256 + k] = lo;
    }
}

// ---------------------------------------------------------------------------
// proj_kernel (unchanged from R9)
// ---------------------------------------------------------------------------
#define P_XH   0
#define P_XL   67584
#define P_WH   135168
#define P_WL   168960
#define P_MASK 202752
#define P_SMEM 203264

__global__ __launch_bounds__(512) void proj_kernel(
    const float* __restrict__ mask,
    const float* __restrict__ ba, const float* __restrict__ bb)
{
    extern __shared__ char smem[];
    const uint32_t sb = smem_u32(smem);
    const int tid  = threadIdx.x;
    const int lane = tid & 31;
    const int wid  = tid >> 5;
    const int i = blockIdx.x;

#pragma unroll
    for (int v = 0; v < 16; v++) {
        const int idx = v * 512 + tid;
        const int buf = idx >> 12;
        const int rem = idx & 4095;
        const int rown = rem >> 5, q = rem & 31;
        const __nv_bfloat16* src = (buf ? g_Xl : g_Xh) +
            (size_t)(rown * 256 + i) * 256 + q * 8;
        CP16(sb + (buf ? P_XL : P_XH) + rown * 528 + q * 16, src);
    }
#pragma unroll
    for (int v = 0; v < 8; v++) {
        const int idx = v * 512 + tid;
        const int buf = idx >> 11;
        const int rem = idx & 2047;
        const int rowo = rem >> 5, q = rem & 31;
        const __nv_bfloat16* src = (buf ? g_Wtl : g_Wth) + rowo * 256 + q * 8;
        CP16(sb + (buf ? P_WL : P_WH) + rowo * 528 + q * 16, src);
    }
    CP_COMMIT();

    if (tid < 128)
        *reinterpret_cast<float*>(smem + P_MASK + tid * 4) = mask[tid * LL + i];

    CP_WAIT(0);
    __syncthreads();

    const int wm = wid >> 2, wn = wid & 3;
    float acc[2][2][4];
#pragma unroll
    for (int fm = 0; fm < 2; fm++)
#pragma unroll
        for (int fn = 0; fn < 2; fn++)
#pragma unroll
            for (int e = 0; e < 4; e++) acc[fm][fn][e] = 0.f;

    const uint32_t rofs = (uint32_t)((lane & 15) * 528 + (lane >> 4) * 16);
    const uint32_t aXh = sb + P_XH + wm * 32 * 528 + rofs;
    const uint32_t aXl = sb + P_XL + wm * 32 * 528 + rofs;
    const uint32_t aWh = sb + P_WH + wn * 16 * 528 + rofs;
    const uint32_t aWl = sb + P_WL + wn * 16 * 528 + rofs;

#pragma unroll
    for (int ks = 0; ks < 16; ks++) {
        uint32_t X_h[2][4], X_l[2][4], W_h[4], W_l[4];
        ldsm4(X_h[0], aXh + ks * 32);
        ldsm4(X_h[1], aXh + 16 * 528 + ks * 32);
        ldsm4(X_l[0], aXl + ks * 32);
        ldsm4(X_l[1], aXl + 16 * 528 + ks * 32);
        ldsm4(W_h, aWh + ks * 32);
        ldsm4(W_l, aWl + ks * 32);
#pragma unroll
        for (int fm = 0; fm < 2; fm++)
#pragma unroll
            for (int fn = 0; fn < 2; fn++) {
                const uint32_t bh0 = W_h[fn], bh1 = W_h[fn + 2];
                const uint32_t bl0 = W_l[fn], bl1 = W_l[fn + 2];
                mma_bf16(acc[fm][fn], X_h[fm], bh0, bh1);
                mma_bf16(acc[fm][fn], X_h[fm], bl0, bl1);
                mma_bf16(acc[fm][fn], X_l[fm], bh0, bh1);
            }
    }

    __syncthreads();

    float* sOut = reinterpret_cast<float*>(smem);
    const float* sMask = reinterpret_cast<const float*>(smem + P_MASK);
#pragma unroll
    for (int fm = 0; fm < 2; fm++)
#pragma unroll
        for (int fn = 0; fn < 2; fn++)
#pragma unroll
            for (int e = 0; e < 4; e++) {
                const int n_loc = wm * 32 + fm * 16 + (lane >> 2) + (e >> 1) * 8;
                const int o     = wn * 16 + fn * 8 + (lane & 3) * 2 + (e & 1);
                const float bias = (o < 32) ? ba[o] : bb[o - 32];
                sOut[o * 132 + n_loc] = (acc[fm][fn][e] + bias) * sMask[n_loc];
            }
    __syncthreads();

    {
        const int o  = tid >> 3;
        const int n0 = (tid & 7) * 16;
        __nv_bfloat16 hb[16], lb[16];
#pragma unroll
        for (int c = 0; c < 16; c++)
            split1(sOut[o * 132 + n0 + c], hb[c], lb[c]);
        __nv_bfloat16* dh = ((o < 32) ? g_Ah : g_Bh) + (size_t)(i * 32 + (o & 31)) * 128 + n0;
        __nv_bfloat16* dl = ((o < 32) ? g_Al : g_Bl) + (size_t)(i * 32 + (o & 31)) * 128 + n0;
        reinterpret_cast<uint4*>(dh)[0] = reinterpret_cast<const uint4*>(hb)[0];
        reinterpret_cast<uint4*>(dh)[1] = reinterpret_cast<const uint4*>(hb)[1];
        reinterpret_cast<uint4*>(dl)[0] = reinterpret_cast<const uint4*>(lb)[0];
        reinterpret_cast<uint4*>(dl)[1] = reinterpret_cast<const uint4*>(lb)[1];
    }
}

// ---------------------------------------------------------------------------
// Fused kernel, 256x128 tile (32 pairs): phase A GEMM in regs -> O bf16 smem
// -> phase B O @ Wo^T with 2-stage Wo streaming.
//
// SMEM (bytes):
//   phase A: Ah [0,69632) Al [69632,139264) Bh [139264,174080) Bl [174080,208896)
//   phase B: Wo stages [0, 73728)  (2 x (h 18432 + l 18432))
//            O  [73728, 205824)    (hi 32x2064, lo 32x2064)
//            pm [205824, 205952)
//            red (reduction) reuses [0, 49152)
// ---------------------------------------------------------------------------
#define F_AH   0
#define F_AL   69632
#define F_BH   139264
#define F_BL   174080
#define FW_ST  36864
#define FW_BUF 18432
#define OFFO   73728
#define OFFOL  (OFFO + 66048)
#define OFFPM  205824
#define F_SMEM 208896

__device__ __forceinline__ void load_wo_chunk(uint32_t sb, int st, int ck, int tid)
{
#pragma unroll
    for (int v = 0; v < 4; v++) {
        const int idx = v * 512 + tid;          // 0..2047
        const int buf = idx >> 10;
        const int rem = idx & 1023;
        const int row = rem >> 3, q = rem & 7;
        const __nv_bfloat16* src = (buf ? g_Wol : g_Woh) + (size_t)row * 1024 + ck * 64 + q * 8;
        CP16(sb + st * FW_ST + buf * FW_BUF + row * 144 + q * 16, src);
    }
    CP_COMMIT();
}

__global__ __launch_bounds__(512) void fused_kernel(
    const float* __restrict__ bo, float* __restrict__ out)
{
    extern __shared__ char smem[];
    const uint32_t sb = smem_u32(smem);
    const int tid  = threadIdx.x;
    const int lane = tid & 31;
    const int wid  = tid >> 5;
    const int bm = blockIdx.y, bn = blockIdx.x;   // bm 0..31, bn 0..63
    const int i0 = bm * 8, j0 = bn * 4;

    // ======================= Phase A loads (2 k-half groups) ================
#pragma unroll
    for (int kh = 0; kh < 2; kh++) {
#pragma unroll
        for (int v = 0; v < 12; v++) {
            const int idx = v * 512 + tid;       // 0..6143
            if (idx < 4096) {                    // A: 2 bufs x 256 rows x 8 q
                const int buf = idx >> 11;
                const int rem = idx & 2047;
                const int row = rem >> 3, q = rem & 7;
                const __nv_bfloat16* src = (buf ? g_Al : g_Ah) +
                    (size_t)(bm * 256 + row) * 128 + kh * 64 + q * 8;
                CP16(sb + (buf ? F_AL : F_AH) + row * 272 + kh * 128 + q * 16, src);
            } else {                             // B: 2 bufs x 128 rows x 8 q
                const int r2  = idx - 4096;
                const int buf = r2 >> 10;
                const int rem = r2 & 1023;
                const int row = rem >> 3, q = rem & 7;
                const __nv_bfloat16* src = (buf ? g_Bl : g_Bh) +
                    (size_t)(bn * 128 + row) * 128 + kh * 64 + q * 8;
                CP16(sb + (buf ? F_BL : F_BH) + row * 272 + kh * 128 + q * 16, src);
            }
        }
        CP_COMMIT();
    }

    // warp tile: wm 0..7 (32 rows, i_loc = wm), wn 0..1 (64 cols = 2 j_loc)
    const int wm = wid >> 1, wn = wid & 1;
    float acc[2][8][4];
#pragma unroll
    for (int fm = 0; fm < 2; fm++)
#pragma unroll
        for (int fn = 0; fn < 8; fn++)
#pragma unroll
            for (int e = 0; e < 4; e++) acc[fm][fn][e] = 0.f;

    const uint32_t rofsA = (uint32_t)((lane & 15) * 272 + (lane >> 4) * 16);
    const uint32_t aAh = sb + F_AH + wm * 32 * 272 + rofsA;
    const uint32_t aAl = sb + F_AL + wm * 32 * 272 + rofsA;
    const uint32_t aBh = sb + F_BH + wn * 64 * 272 + rofsA;
    const uint32_t aBl = sb + F_BL + wn * 64 * 272 + rofsA;

    CP_WAIT(1);
    __syncthreads();

#pragma unroll
    for (int ks = 0; ks < 8; ks++) {
        if (ks == 4) { CP_WAIT(0); __syncthreads(); }
        uint32_t A_h[2][4], A_l[2][4];
        ldsm4(A_h[0], aAh + ks * 32);
        ldsm4(A_h[1], aAh + 16 * 272 + ks * 32);
        ldsm4(A_l[0], aAl + ks * 32);
        ldsm4(A_l[1], aAl + 16 * 272 + ks * 32);
#pragma unroll
        for (int bh2 = 0; bh2 < 2; bh2++) {      // 2 halves of the 64-col span
            uint32_t B_h[2][4], B_l[2][4];
            const uint32_t bo0 = (uint32_t)(bh2 * 32 * 272 + ks * 32);
            ldsm4(B_h[0], aBh + bo0);
            ldsm4(B_h[1], aBh + 16 * 272 + bo0);
            ldsm4(B_l[0], aBl + bo0);
            ldsm4(B_l[1], aBl + 16 * 272 + bo0);
#pragma unroll
            for (int fm = 0; fm < 2; fm++)
#pragma unroll
                for (int fl = 0; fl < 4; fl++) {
                    const int fn = bh2 * 4 + fl;
                    const uint32_t bh0 = B_h[fl >> 1][fl & 1];
                    const uint32_t bh1 = B_h[fl >> 1][(fl & 1) + 2];
                    const uint32_t bl0 = B_l[fl >> 1][fl & 1];
                    const uint32_t bl1 = B_l[fl >> 1][(fl & 1) + 2];
                    mma_bf16(acc[fm][fn], A_h[fm], bh0, bh1);
                    mma_bf16(acc[fm][fn], A_h[fm], bl0, bl1);
                    mma_bf16(acc[fm][fn], A_l[fm], bh0, bh1);
                }
        }
    }

    __syncthreads();   // all A/B smem reads done

    // prefetch first two Wo chunks into [0, 73728)
    load_wo_chunk(sb, 0, 0, tid);
    load_wo_chunk(sb, 1, 1, tid);

    // ---- O spill: pair p = wm*4 + wn*2 + (fn>>2), k = c*32 + d ----
#pragma unroll
    for (int fm = 0; fm < 2; fm++)
#pragma unroll
        for (int fn = 0; fn < 8; fn++) {
            const int p = wm * 4 + wn * 2 + (fn >> 2);
            char* oh = smem + OFFO  + p * 2064;
            char* ol = smem + OFFOL + p * 2064;
#pragma unroll
            for (int half = 0; half < 2; half++) {
                const int c = fm * 16 + (lane >> 2) + half * 8;
                const int d = (fn & 3) * 8 + (lane & 3) * 2;
                const int k = c * 32 + d;
                __nv_bfloat162 h2, l2;
                split1(acc[fm][fn][half * 2 + 0], h2.x, l2.x);
                split1(acc[fm][fn][half * 2 + 1], h2.y, l2.y);
                *reinterpret_cast<__nv_bfloat162*>(oh + 2 * k) = h2;
                *reinterpret_cast<__nv_bfloat162*>(ol + 2 * k) = l2;
            }
        }
    if (tid < 32) {
        const int ii = i0 + (tid >> 2), jj = j0 + (tid & 3);
        *reinterpret_cast<float*>(smem + OFFPM + tid * 4) =
            1.f / (g_pm[ii * LL + jj] + 1e-8f);
    }
    __syncthreads();

    // ======================= Phase B ========================================
    // warp: wn2 = wid&3 (32 z), kc = wid>>2 (k-split 4; 1 ks per 64k chunk)
    const int wn2 = wid & 3;
    const int kc  = wid >> 2;

    float acc2[2][4][4];
#pragma unroll
    for (int fm = 0; fm < 2; fm++)
#pragma unroll
        for (int fn = 0; fn < 4; fn++)
#pragma unroll
            for (int e = 0; e < 4; e++) acc2[fm][fn][e] = 0.f;

    const uint32_t aOh = sb + OFFO + (uint32_t)((lane & 15) * 2064 + (lane >> 4) * 16);
    const uint32_t aOl = aOh + 66048;
    const uint32_t rofsW = (uint32_t)(wn2 * 32 * 144 + (lane & 15) * 144 + (lane >> 4) * 16);

    for (int ck = 0; ck < 16; ck++) {
        const int st = ck & 1;
        if (ck < 15) CP_WAIT(1); else CP_WAIT(0);
        __syncthreads();

        uint32_t A_h[2][4], A_l[2][4], B_h[2][4], B_l[2][4];
        const uint32_t ao = (uint32_t)(ck * 128 + kc * 32);
        ldsm4(A_h[0], aOh + ao);
        ldsm4(A_h[1], aOh + 16 * 2064 + ao);
        ldsm4(A_l[0], aOl + ao);
        ldsm4(A_l[1], aOl + 16 * 2064 + ao);
        const uint32_t bwh = sb + st * FW_ST + rofsW + kc * 32;
        ldsm4(B_h[0], bwh);
        ldsm4(B_h[1], bwh + 16 * 144);
        ldsm4(B_l[0], bwh + FW_BUF);
        ldsm4(B_l[1], bwh + FW_BUF + 16 * 144);

#pragma unroll
        for (int fm = 0; fm < 2; fm++)
#pragma unroll
            for (int fn = 0; fn < 4; fn++) {
                const uint32_t bh0 = B_h[fn >> 1][fn & 1];
                const uint32_t bh1 = B_h[fn >> 1][(fn & 1) + 2];
                const uint32_t bl0 = B_l[fn >> 1][fn & 1];
                const uint32_t bl1 = B_l[fn >> 1][(fn & 1) + 2];
                mma_bf16(acc2[fm][fn], A_h[fm], bh0, bh1);
                mma_bf16(acc2[fm][fn], A_h[fm], bl0, bl1);
                mma_bf16(acc2[fm][fn], A_l[fm], bh0, bh1);
            }

        __syncthreads();   // stage st reads done
        if (ck + 2 < 16) load_wo_chunk(sb, st, ck + 2, tid);
    }

    // ---- k-split reduction via smem [0, 49152) (Wo region, now free) ----
    float* red = reinterpret_cast<float*>(smem);
    if (kc > 0) {
#pragma unroll
        for (int fm = 0; fm < 2; fm++)
#pragma unroll
            for (int fn = 0; fn < 4; fn++)
#pragma unroll
                for (int e = 0; e < 4; e++) {
                    const int p = fm * 16 + (lane >> 2) + (e >> 1) * 8;
                    const int z = wn2 * 32 + fn * 8 + (lane & 3) * 2 + (e & 1);
                    red[(kc - 1) * 4096 + p * 128 + z] = acc2[fm][fn][e];
                }
    }
    __syncthreads();
    if (kc == 0) {
        const float* pmv = reinterpret_cast<const float*>(smem + OFFPM);
#pragma unroll
        for (int fm = 0; fm < 2; fm++)
#pragma unroll
            for (int fn = 0; fn < 4; fn++)
#pragma unroll
                for (int e = 0; e < 4; e++) {
                    const int p = fm * 16 + (lane >> 2) + (e >> 1) * 8;
                    const int z = wn2 * 32 + fn * 8 + (lane & 3) * 2 + (e & 1);
                    acc2[fm][fn][e] += red[p * 128 + z]
                                     + red[4096 + p * 128 + z]
                                     + red[8192 + p * 128 + z];
                }
#pragma unroll
        for (int fm = 0; fm < 2; fm++)
#pragma unroll
            for (int fn = 0; fn < 4; fn++)
#pragma unroll
                for (int prow = 0; prow < 2; prow++) {
                    const int p  = fm * 16 + (lane >> 2) + prow * 8;
                    const int ii = i0 + (p >> 2), jj = j0 + (p & 3);
                    const float inv = pmv[p];
                    const int z = wn2 * 32 + fn * 8 + (lane & 3) * 2;
                    float2 res;
                    res.x = acc2[fm][fn][prow * 2 + 0] * inv + bo[z];
                    res.y = acc2[fm][fn][prow * 2 + 1] * inv + bo[z + 1];
                    *reinterpret_cast<float2*>(out + (size_t)(ii * LL + jj) * CZ + z) = res;
                }
    }
}

// ---------------------------------------------------------------------------
extern "C" void kernel_launch(void* const* d_in, const int* in_sizes, int n_in,
                              void* d_out, int out_size)
{
    const float* m     = (const float*)d_in[0];
    const float* mask  = (const float*)d_in[1];
    const float* gamma = (const float*)d_in[2];
    const float* beta  = (const float*)d_in[3];
    const float* Wa    = (const float*)d_in[4];
    const float* ba    = (const float*)d_in[5];
    const float* Wb    = (const float*)d_in[6];
    const float* bb    = (const float*)d_in[7];
    const float* Wo    = (const float*)d_in[8];
    const float* bo    = (const float*)d_in[9];
    float* out = (float*)d_out;

    cudaFuncSetAttribute(proj_kernel,  cudaFuncAttributeMaxDynamicSharedMemorySize, P_SMEM);
    cudaFuncSetAttribute(fused_kernel, cudaFuncAttributeMaxDynamicSharedMemorySize, F_SMEM);

    ln_kernel<<<4096, 256>>>(m, gamma, beta);
    prep_kernel<<<384, 256>>>(mask, Wo, Wa, Wb);
    proj_kernel<<<256, 512, P_SMEM>>>(mask, ba, bb);
    fused_kernel<<<dim3(64, 32), 512, F_SMEM>>>(bo, out);
}

// round 12
// speedup vs baseline: 1.5833x; 1.1446x over previous
#include <cuda_runtime.h>
#include <cuda_bf16.h>
#include <cstdint>

#define NN 128
#define LL 256
#define CM 256
#define CH 32
#define CZ 128
#define RTOT 8192   // LL*CH

// ---------------- global scratch ----------------
__device__ __align__(16) __nv_bfloat16 g_Xh[(size_t)32768 * 256];  // LN(x) hi
__device__ __align__(16) __nv_bfloat16 g_Xl[(size_t)32768 * 256];  // LN(x) lo
__device__ __align__(16) __nv_bfloat16 g_Wth[64 * 256];   // [o][k]  ([Wa|Wb]^T)
__device__ __align__(16) __nv_bfloat16 g_Wtl[64 * 256];
__device__ __align__(16) __nv_bfloat16 g_Ah[RTOT * NN];   // [r=i*32+h][n]
__device__ __align__(16) __nv_bfloat16 g_Al[RTOT * NN];
__device__ __align__(16) __nv_bfloat16 g_Bh[RTOT * NN];
__device__ __align__(16) __nv_bfloat16 g_Bl[RTOT * NN];
__device__ __align__(16) __nv_bfloat16 g_Woh[CZ * 1024];  // [z][k] (Wo^T)
__device__ __align__(16) __nv_bfloat16 g_Wol[CZ * 1024];
__device__ float g_pm[LL * LL];

// ---------------- helpers ----------------
__device__ __forceinline__ uint32_t smem_u32(const void* p) {
    uint32_t a;
    asm("{ .reg .u64 t; cvta.to.shared.u64 t, %1; cvt.u32.u64 %0, t; }" : "=r"(a) : "l"(p));
    return a;
}
__device__ __forceinline__ void ldsm4(uint32_t* r, uint32_t addr) {
    asm volatile("ldmatrix.sync.aligned.m8n8.x4.shared.b16 {%0,%1,%2,%3}, [%4];"
        : "=r"(r[0]), "=r"(r[1]), "=r"(r[2]), "=r"(r[3]) : "r"(addr));
}
__device__ __forceinline__ void mma_bf16(float* d, const uint32_t* a,
                                         uint32_t b0, uint32_t b1) {
    asm volatile(
        "mma.sync.aligned.m16n8k16.row.col.f32.bf16.bf16.f32 "
        "{%0,%1,%2,%3}, {%4,%5,%6,%7}, {%8,%9}, {%0,%1,%2,%3};"
        : "+f"(d[0]), "+f"(d[1]), "+f"(d[2]), "+f"(d[3])
        : "r"(a[0]), "r"(a[1]), "r"(a[2]), "r"(a[3]), "r"(b0), "r"(b1));
}
#define CP16(dst, src) asm volatile("cp.async.cg.shared.global [%0], [%1], 16;" :: "r"(dst), "l"(src))
#define CP_COMMIT()    asm volatile("cp.async.commit_group;" ::: "memory")
#define CP_WAIT(n)     asm volatile("cp.async.wait_group %0;" :: "n"(n) : "memory")

__device__ __forceinline__ void split1(float x, __nv_bfloat16& h, __nv_bfloat16& l) {
    h = __float2bfloat16(x);
    l = __float2bfloat16(x - __bfloat162float(h));
}

// ---------------------------------------------------------------------------
// ln_kernel: warp-per-row LayerNorm (unchanged)
// ---------------------------------------------------------------------------
__global__ __launch_bounds__(256) void ln_kernel(
    const float* __restrict__ m, const float* __restrict__ gamma,
    const float* __restrict__ beta)
{
    const int row  = blockIdx.x * 8 + (threadIdx.x >> 5);
    const int lane = threadIdx.x & 31;
    const size_t base = (size_t)row * 256 + lane * 8;

    const float4 v0 = *reinterpret_cast<const float4*>(m + base);
    const float4 v1 = *reinterpret_cast<const float4*>(m + base + 4);
    float x[8] = {v0.x, v0.y, v0.z, v0.w, v1.x, v1.y, v1.z, v1.w};

    float s = 0.f, q = 0.f;
#pragma unroll
    for (int c = 0; c < 8; c++) { s += x[c]; q += x[c] * x[c]; }
#pragma unroll
    for (int o = 16; o > 0; o >>= 1) {
        s += __shfl_xor_sync(0xffffffffu, s, o);
        q += __shfl_xor_sync(0xffffffffu, q, o);
    }
    const float mean = s * (1.f / 256.f);
    const float var  = q * (1.f / 256.f) - mean * mean;
    const float rstd = rsqrtf(var + 1e-5f);

    const float4 g0 = *reinterpret_cast<const float4*>(gamma + lane * 8);
    const float4 g1 = *reinterpret_cast<const float4*>(gamma + lane * 8 + 4);
    const float4 b0 = *reinterpret_cast<const float4*>(beta + lane * 8);
    const float4 b1 = *reinterpret_cast<const float4*>(beta + lane * 8 + 4);
    const float gm[8] = {g0.x, g0.y, g0.z, g0.w, g1.x, g1.y, g1.z, g1.w};
    const float bt[8] = {b0.x, b0.y, b0.z, b0.w, b1.x, b1.y, b1.z, b1.w};

    __nv_bfloat16 hb[8], lb[8];
#pragma unroll
    for (int c = 0; c < 8; c++) {
        const float y = (x[c] - mean) * rstd * gm[c] + bt[c];
        split1(y, hb[c], lb[c]);
    }
    *reinterpret_cast<uint4*>(g_Xh + base) = *reinterpret_cast<const uint4*>(hb);
    *reinterpret_cast<uint4*>(g_Xl + base) = *reinterpret_cast<const uint4*>(lb);
}

// ---------------------------------------------------------------------------
// Prep: pair-mask table + Wo^T bf16 split + [Wa|Wb]^T bf16 split (unchanged)
// ---------------------------------------------------------------------------
__global__ __launch_bounds__(256) void prep_kernel(
    const float* __restrict__ mask, const float* __restrict__ Wo,
    const float* __restrict__ Wa, const float* __restrict__ Wb)
{
    const int t = threadIdx.x;
    if (blockIdx.x < 256) {
        const int i = blockIdx.x, j = t;
        float s = 0.f;
        for (int n = 0; n < NN; n++) s += mask[n * LL + i] * mask[n * LL + j];
        g_pm[i * LL + j] = s;
    } else if (blockIdx.x < 320) {
        const int b = blockIdx.x - 256;
#pragma unroll
        for (int v = 0; v < 8; v++) {
            const int e = b * 2048 + v * 256 + t;
            const float val = Wo[e];
            const int k = e >> 7, z = e & 127;
            __nv_bfloat16 hi, lo;
            split1(val, hi, lo);
            g_Woh[z * 1024 + k] = hi;
            g_Wol[z * 1024 + k] = lo;
        }
    } else {
        const int idx = (blockIdx.x - 320) * 256 + t;
        const int o = idx >> 8, k = idx & 255;
        const float val = (o < 32) ? Wa[k * 32 + o] : Wb[k * 32 + (o - 32)];
        __nv_bfloat16 hi, lo;
        split1(val, hi, lo);
        g_Wth[o * 256 + k] = hi;
        g_Wtl[o * 256 + k] = lo;
    }
}

// ---------------------------------------------------------------------------
// proj_kernel (unchanged from R9)
// ---------------------------------------------------------------------------
#define P_XH   0
#define P_XL   67584
#define P_WH   135168
#define P_WL   168960
#define P_MASK 202752
#define P_SMEM 203264

__global__ __launch_bounds__(512) void proj_kernel(
    const float* __restrict__ mask,
    const float* __restrict__ ba, const float* __restrict__ bb)
{
    extern __shared__ char smem[];
    const uint32_t sb = smem_u32(smem);
    const int tid  = threadIdx.x;
    const int lane = tid & 31;
    const int wid  = tid >> 5;
    const int i = blockIdx.x;

#pragma unroll
    for (int v = 0; v < 16; v++) {
        const int idx = v * 512 + tid;
        const int buf = idx >> 12;
        const int rem = idx & 4095;
        const int rown = rem >> 5, q = rem & 31;
        const __nv_bfloat16* src = (buf ? g_Xl : g_Xh) +
            (size_t)(rown * 256 + i) * 256 + q * 8;
        CP16(sb + (buf ? P_XL : P_XH) + rown * 528 + q * 16, src);
    }
#pragma unroll
    for (int v = 0; v < 8; v++) {
        const int idx = v * 512 + tid;
        const int buf = idx >> 11;
        const int rem = idx & 2047;
        const int rowo = rem >> 5, q = rem & 31;
        const __nv_bfloat16* src = (buf ? g_Wtl : g_Wth) + rowo * 256 + q * 8;
        CP16(sb + (buf ? P_WL : P_WH) + rowo * 528 + q * 16, src);
    }
    CP_COMMIT();

    if (tid < 128)
        *reinterpret_cast<float*>(smem + P_MASK + tid * 4) = mask[tid * LL + i];

    CP_WAIT(0);
    __syncthreads();

    const int wm = wid >> 2, wn = wid & 3;
    float acc[2][2][4];
#pragma unroll
    for (int fm = 0; fm < 2; fm++)
#pragma unroll
        for (int fn = 0; fn < 2; fn++)
#pragma unroll
            for (int e = 0; e < 4; e++) acc[fm][fn][e] = 0.f;

    const uint32_t rofs = (uint32_t)((lane & 15) * 528 + (lane >> 4) * 16);
    const uint32_t aXh = sb + P_XH + wm * 32 * 528 + rofs;
    const uint32_t aXl = sb + P_XL + wm * 32 * 528 + rofs;
    const uint32_t aWh = sb + P_WH + wn * 16 * 528 + rofs;
    const uint32_t aWl = sb + P_WL + wn * 16 * 528 + rofs;

#pragma unroll
    for (int ks = 0; ks < 16; ks++) {
        uint32_t X_h[2][4], X_l[2][4], W_h[4], W_l[4];
        ldsm4(X_h[0], aXh + ks * 32);
        ldsm4(X_h[1], aXh + 16 * 528 + ks * 32);
        ldsm4(X_l[0], aXl + ks * 32);
        ldsm4(X_l[1], aXl + 16 * 528 + ks * 32);
        ldsm4(W_h, aWh + ks * 32);
        ldsm4(W_l, aWl + ks * 32);
#pragma unroll
        for (int fm = 0; fm < 2; fm++)
#pragma unroll
            for (int fn = 0; fn < 2; fn++) {
                const uint32_t bh0 = W_h[fn], bh1 = W_h[fn + 2];
                const uint32_t bl0 = W_l[fn], bl1 = W_l[fn + 2];
                mma_bf16(acc[fm][fn], X_h[fm], bh0, bh1);
                mma_bf16(acc[fm][fn], X_h[fm], bl0, bl1);
                mma_bf16(acc[fm][fn], X_l[fm], bh0, bh1);
            }
    }

    __syncthreads();

    float* sOut = reinterpret_cast<float*>(smem);
    const float* sMask = reinterpret_cast<const float*>(smem + P_MASK);
#pragma unroll
    for (int fm = 0; fm < 2; fm++)
#pragma unroll
        for (int fn = 0; fn < 2; fn++)
#pragma unroll
            for (int e = 0; e < 4; e++) {
                const int n_loc = wm * 32 + fm * 16 + (lane >> 2) + (e >> 1) * 8;
                const int o     = wn * 16 + fn * 8 + (lane & 3) * 2 + (e & 1);
                const float bias = (o < 32) ? ba[o] : bb[o - 32];
                sOut[o * 132 + n_loc] = (acc[fm][fn][e] + bias) * sMask[n_loc];
            }
    __syncthreads();

    {
        const int o  = tid >> 3;
        const int n0 = (tid & 7) * 16;
        __nv_bfloat16 hb[16], lb[16];
#pragma unroll
        for (int c = 0; c < 16; c++)
            split1(sOut[o * 132 + n0 + c], hb[c], lb[c]);
        __nv_bfloat16* dh = ((o < 32) ? g_Ah : g_Bh) + (size_t)(i * 32 + (o & 31)) * 128 + n0;
        __nv_bfloat16* dl = ((o < 32) ? g_Al : g_Bl) + (size_t)(i * 32 + (o & 31)) * 128 + n0;
        reinterpret_cast<uint4*>(dh)[0] = reinterpret_cast<const uint4*>(hb)[0];
        reinterpret_cast<uint4*>(dh)[1] = reinterpret_cast<const uint4*>(hb)[1];
        reinterpret_cast<uint4*>(dl)[0] = reinterpret_cast<const uint4*>(lb)[0];
        reinterpret_cast<uint4*>(dl)[1] = reinterpret_cast<const uint4*>(lb)[1];
    }
}

// ---------------------------------------------------------------------------
// Fused kernel, 256x128 tile (32 pairs).
// Phase A: GEMM in regs (barrier-pipelined, as R10).
// Phase B: barrier-free per-warp Wo streaming (R11) + ONE __syncthreads
//   between the mainloop and the k-split reduction (the R11 bug: reduction
//   writes into [0,49K) overlap stage buffers other warps still read).
//
// SMEM (bytes):
//   phase A: Ah [0,69632) Al [69632,139264) Bh [139264,174080) Bl [174080,208896)
//   phase B: warp Wo stages [0, 65536): st*32768 + wid*2048 (hi +0, lo +1024)
//            O  [65536, 197632)  (hi 32x2064, lo 32x2064)
//            pm [197632, 197760)
//            red (reduction) reuses [0, 49152) AFTER the post-loop barrier
// ---------------------------------------------------------------------------
#define F_AH   0
#define F_AL   69632
#define F_BH   139264
#define F_BL   174080
#define OFFO   65536
#define OFFOL  (OFFO + 66048)
#define OFFPM  197632
#define F_SMEM 208896

// per-warp Wo slice load: 32 z-rows x 16 k (hi+lo), 16B-swizzled 32B-pitch rows
__device__ __forceinline__ void load_wo_slice(uint32_t wstage0, int st, int ck,
                                              int wn2, int kc, int lane)
{
    const uint32_t wbase = wstage0 + st * 32768;
#pragma unroll
    for (int v = 0; v < 4; v++) {
        const int idx = v * 32 + lane;      // 0..127
        const int buf = idx >> 6;           // 0 = hi, 1 = lo
        const int rem = idx & 63;
        const int r = rem >> 1, h = rem & 1;
        const int hs = h ^ ((r >> 2) & 1);  // swizzle
        const __nv_bfloat16* src = (buf ? g_Wol : g_Woh)
            + (size_t)(wn2 * 32 + r) * 1024 + ck * 64 + kc * 16 + h * 8;
        CP16(wbase + buf * 1024 + r * 32 + hs * 16, src);
    }
    CP_COMMIT();
}

__global__ __launch_bounds__(512) void fused_kernel(
    const float* __restrict__ bo, float* __restrict__ out)
{
    extern __shared__ char smem[];
    const uint32_t sb = smem_u32(smem);
    const int tid  = threadIdx.x;
    const int lane = tid & 31;
    const int wid  = tid >> 5;
    const int bm = blockIdx.y, bn = blockIdx.x;   // bm 0..31, bn 0..63
    const int i0 = bm * 8, j0 = bn * 4;

    // ======================= Phase A (as R10) ===============================
#pragma unroll
    for (int kh = 0; kh < 2; kh++) {
#pragma unroll
        for (int v = 0; v < 12; v++) {
            const int idx = v * 512 + tid;
            if (idx < 4096) {
                const int buf = idx >> 11;
                const int rem = idx & 2047;
                const int row = rem >> 3, q = rem & 7;
                const __nv_bfloat16* src = (buf ? g_Al : g_Ah) +
                    (size_t)(bm * 256 + row) * 128 + kh * 64 + q * 8;
                CP16(sb + (buf ? F_AL : F_AH) + row * 272 + kh * 128 + q * 16, src);
            } else {
                const int r2  = idx - 4096;
                const int buf = r2 >> 10;
                const int rem = r2 & 1023;
                const int row = rem >> 3, q = rem & 7;
                const __nv_bfloat16* src = (buf ? g_Bl : g_Bh) +
                    (size_t)(bn * 128 + row) * 128 + kh * 64 + q * 8;
                CP16(sb + (buf ? F_BL : F_BH) + row * 272 + kh * 128 + q * 16, src);
            }
        }
        CP_COMMIT();
    }

    const int wm = wid >> 1, wn = wid & 1;
    float acc[2][8][4];
#pragma unroll
    for (int fm = 0; fm < 2; fm++)
#pragma unroll
        for (int fn = 0; fn < 8; fn++)
#pragma unroll
            for (int e = 0; e < 4; e++) acc[fm][fn][e] = 0.f;

    const uint32_t rofsA = (uint32_t)((lane & 15) * 272 + (lane >> 4) * 16);
    const uint32_t aAh = sb + F_AH + wm * 32 * 272 + rofsA;
    const uint32_t aAl = sb + F_AL + wm * 32 * 272 + rofsA;
    const uint32_t aBh = sb + F_BH + wn * 64 * 272 + rofsA;
    const uint32_t aBl = sb + F_BL + wn * 64 * 272 + rofsA;

    CP_WAIT(1);
    __syncthreads();

#pragma unroll
    for (int ks = 0; ks < 8; ks++) {
        if (ks == 4) { CP_WAIT(0); __syncthreads(); }
        uint32_t A_h[2][4], A_l[2][4];
        ldsm4(A_h[0], aAh + ks * 32);
        ldsm4(A_h[1], aAh + 16 * 272 + ks * 32);
        ldsm4(A_l[0], aAl + ks * 32);
        ldsm4(A_l[1], aAl + 16 * 272 + ks * 32);
#pragma unroll
        for (int bh2 = 0; bh2 < 2; bh2++) {
            uint32_t B_h[2][4], B_l[2][4];
            const uint32_t bo0 = (uint32_t)(bh2 * 32 * 272 + ks * 32);
            ldsm4(B_h[0], aBh + bo0);
            ldsm4(B_h[1], aBh + 16 * 272 + bo0);
            ldsm4(B_l[0], aBl + bo0);
            ldsm4(B_l[1], aBl + 16 * 272 + bo0);
#pragma unroll
            for (int fm = 0; fm < 2; fm++)
#pragma unroll
                for (int fl = 0; fl < 4; fl++) {
                    const int fn = bh2 * 4 + fl;
                    const uint32_t bh0 = B_h[fl >> 1][fl & 1];
                    const uint32_t bh1 = B_h[fl >> 1][(fl & 1) + 2];
                    const uint32_t bl0 = B_l[fl >> 1][fl & 1];
                    const uint32_t bl1 = B_l[fl >> 1][(fl & 1) + 2];
                    mma_bf16(acc[fm][fn], A_h[fm], bh0, bh1);
                    mma_bf16(acc[fm][fn], A_h[fm], bl0, bl1);
                    mma_bf16(acc[fm][fn], A_l[fm], bh0, bh1);
                }
        }
    }

    __syncthreads();   // all A/B smem reads done; stage region reusable

    // ---- phase B prologue: each warp streams its own first 2 chunks ----
    const int wn2 = wid & 3;
    const int kc  = wid >> 2;
    const uint32_t wstage0 = sb + wid * 2048;
    load_wo_slice(wstage0, 0, 0, wn2, kc, lane);
    load_wo_slice(wstage0, 1, 1, wn2, kc, lane);

    // ---- O spill: pair p = wm*4 + wn*2 + (fn>>2), k = c*32 + d ----
#pragma unroll
    for (int fm = 0; fm < 2; fm++)
#pragma unroll
        for (int fn = 0; fn < 8; fn++) {
            const int p = wm * 4 + wn * 2 + (fn >> 2);
            char* oh = smem + OFFO  + p * 2064;
            char* ol = smem + OFFOL + p * 2064;
#pragma unroll
            for (int half = 0; half < 2; half++) {
                const int c = fm * 16 + (lane >> 2) + half * 8;
                const int d = (fn & 3) * 8 + (lane & 3) * 2;
                const int k = c * 32 + d;
                __nv_bfloat162 h2, l2;
                split1(acc[fm][fn][half * 2 + 0], h2.x, l2.x);
                split1(acc[fm][fn][half * 2 + 1], h2.y, l2.y);
                *reinterpret_cast<__nv_bfloat162*>(oh + 2 * k) = h2;
                *reinterpret_cast<__nv_bfloat162*>(ol + 2 * k) = l2;
            }
        }
    if (tid < 32) {
        const int ii = i0 + (tid >> 2), jj = j0 + (tid & 3);
        *reinterpret_cast<float*>(smem + OFFPM + tid * 4) =
            1.f / (g_pm[ii * LL + jj] + 1e-8f);
    }
    __syncthreads();   // O + pm visible to all warps

    // ======================= Phase B: barrier-free loop =====================
    float acc2[2][4][4];
#pragma unroll
    for (int fm = 0; fm < 2; fm++)
#pragma unroll
        for (int fn = 0; fn < 4; fn++)
#pragma unroll
            for (int e = 0; e < 4; e++) acc2[fm][fn][e] = 0.f;

    const uint32_t aOh = sb + OFFO + (uint32_t)((lane & 15) * 2064 + (lane >> 4) * 16);
    const uint32_t aOl = aOh + 66048;
    const int rB  = lane & 15;
    const int cbB = lane >> 4;
    const uint32_t bofs = (uint32_t)(rB * 32 + ((cbB ^ ((rB >> 2) & 1)) << 4));

    for (int ck = 0; ck < 16; ck++) {
        const int st = ck & 1;
        if (ck == 15) CP_WAIT(0); else CP_WAIT(1);
        __syncwarp();

        uint32_t A_h[2][4], A_l[2][4], B_h[2][4], B_l[2][4];
        const uint32_t ao = (uint32_t)(ck * 128 + kc * 32);
        ldsm4(A_h[0], aOh + ao);
        ldsm4(A_h[1], aOh + 16 * 2064 + ao);
        ldsm4(A_l[0], aOl + ao);
        ldsm4(A_l[1], aOl + 16 * 2064 + ao);
        const uint32_t wb = wstage0 + st * 32768;
        ldsm4(B_h[0], wb + bofs);
        ldsm4(B_h[1], wb + 512 + bofs);
        ldsm4(B_l[0], wb + 1024 + bofs);
        ldsm4(B_l[1], wb + 1536 + bofs);

        if (ck + 2 < 16) load_wo_slice(wstage0, st, ck + 2, wn2, kc, lane);

#pragma unroll
        for (int fm = 0; fm < 2; fm++)
#pragma unroll
            for (int fn = 0; fn < 4; fn++) {
                const uint32_t bh0 = B_h[fn >> 1][fn & 1];
                const uint32_t bh1 = B_h[fn >> 1][(fn & 1) + 2];
                const uint32_t bl0 = B_l[fn >> 1][fn & 1];
                const uint32_t bl1 = B_l[fn >> 1][(fn & 1) + 2];
                mma_bf16(acc2[fm][fn], A_h[fm], bh0, bh1);
                mma_bf16(acc2[fm][fn], A_h[fm], bl0, bl1);
                mma_bf16(acc2[fm][fn], A_l[fm], bh0, bh1);
            }
    }

    // THE FIX: all warps must finish reading their stage buffers before the
    // reduction reuses [0, 49152) as scratch.
    __syncthreads();

    // ---- k-split reduction via smem [0, 49152) ----
    float* red = reinterpret_cast<float*>(smem);
    if (kc > 0) {
#pragma unroll
        for (int fm = 0; fm < 2; fm++)
#pragma unroll
            for (int fn = 0; fn < 4; fn++)
#pragma unroll
                for (int e = 0; e < 4; e++) {
                    const int p = fm * 16 + (lane >> 2) + (e >> 1) * 8;
                    const int z = wn2 * 32 + fn * 8 + (lane & 3) * 2 + (e & 1);
                    red[(kc - 1) * 4096 + p * 128 + z] = acc2[fm][fn][e];
                }
    }
    __syncthreads();
    if (kc == 0) {
        const float* pmv = reinterpret_cast<const float*>(smem + OFFPM);
#pragma unroll
        for (int fm = 0; fm < 2; fm++)
#pragma unroll
            for (int fn = 0; fn < 4; fn++)
#pragma unroll
                for (int e = 0; e < 4; e++) {
                    const int p = fm * 16 + (lane >> 2) + (e >> 1) * 8;
                    const int z = wn2 * 32 + fn * 8 + (lane & 3) * 2 + (e & 1);
                    acc2[fm][fn][e] += red[p * 128 + z]
                                     + red[4096 + p * 128 + z]
                                     + red[8192 + p * 128 + z];
                }
#pragma unroll
        for (int fm = 0; fm < 2; fm++)
#pragma unroll
            for (int fn = 0; fn < 4; fn++)
#pragma unroll
                for (int prow = 0; prow < 2; prow++) {
                    const int p  = fm * 16 + (lane >> 2) + prow * 8;
                    const int ii = i0 + (p >> 2), jj = j0 + (p & 3);
                    const float inv = pmv[p];
                    const int z = wn2 * 32 + fn * 8 + (lane & 3) * 2;
                    float2 res;
                    res.x = acc2[fm][fn][prow * 2 + 0] * inv + bo[z];
                    res.y = acc2[fm][fn][prow * 2 + 1] * inv + bo[z + 1];
                    *reinterpret_cast<float2*>(out + (size_t)(ii * LL + jj) * CZ + z) = res;
                }
    }
}

// ---------------------------------------------------------------------------
extern "C" void kernel_launch(void* const* d_in, const int* in_sizes, int n_in,
                              void* d_out, int out_size)
{
    const float* m     = (const float*)d_in[0];
    const float* mask  = (const float*)d_in[1];
    const float* gamma = (const float*)d_in[2];
    const float* beta  = (const float*)d_in[3];
    const float* Wa    = (const float*)d_in[4];
    const float* ba    = (const float*)d_in[5];
    const float* Wb    = (const float*)d_in[6];
    const float* bb    = (const float*)d_in[7];
    const float* Wo    = (const float*)d_in[8];
    const float* bo    = (const float*)d_in[9];
    float* out = (float*)d_out;

    cudaFuncSetAttribute(proj_kernel,  cudaFuncAttributeMaxDynamicSharedMemorySize, P_SMEM);
    cudaFuncSetAttribute(fused_kernel, cudaFuncAttributeMaxDynamicSharedMemorySize, F_SMEM);

    ln_kernel<<<4096, 256>>>(m, gamma, beta);
    prep_kernel<<<384, 256>>>(mask, Wo, Wa, Wb);
    proj_kernel<<<256, 512, P_SMEM>>>(mask, ba, bb);
    fused_kernel<<<dim3(64, 32), 512, F_SMEM>>>(bo, out);
}

// round 13
// speedup vs baseline: 1.6012x; 1.0113x over previous
#include <cuda_runtime.h>
#include <cuda_bf16.h>
#include <cstdint>

#define NN 128
#define LL 256
#define CM 256
#define CH 32
#define CZ 128
#define RTOT 8192   // LL*CH

// ---------------- global scratch ----------------
__device__ __align__(16) __nv_bfloat16 g_Xh[(size_t)32768 * 256];  // LN(x) hi
__device__ __align__(16) __nv_bfloat16 g_Xl[(size_t)32768 * 256];  // LN(x) lo
__device__ __align__(16) __nv_bfloat16 g_Wth[64 * 256];   // [o][k]  ([Wa|Wb]^T)
__device__ __align__(16) __nv_bfloat16 g_Wtl[64 * 256];
__device__ __align__(16) __nv_bfloat16 g_Ah[RTOT * NN];   // [r=i*32+h][n]
__device__ __align__(16) __nv_bfloat16 g_Al[RTOT * NN];
__device__ __align__(16) __nv_bfloat16 g_Bh[RTOT * NN];
__device__ __align__(16) __nv_bfloat16 g_Bl[RTOT * NN];
__device__ __align__(16) __nv_bfloat16 g_Woh[CZ * 1024];  // [z][k] (Wo^T)
__device__ __align__(16) __nv_bfloat16 g_Wol[CZ * 1024];
__device__ float g_pm[LL * LL];

// ---------------- helpers ----------------
__device__ __forceinline__ uint32_t smem_u32(const void* p) {
    uint32_t a;
    asm("{ .reg .u64 t; cvta.to.shared.u64 t, %1; cvt.u32.u64 %0, t; }" : "=r"(a) : "l"(p));
    return a;
}
__device__ __forceinline__ void ldsm4(uint32_t* r, uint32_t addr) {
    asm volatile("ldmatrix.sync.aligned.m8n8.x4.shared.b16 {%0,%1,%2,%3}, [%4];"
        : "=r"(r[0]), "=r"(r[1]), "=r"(r[2]), "=r"(r[3]) : "r"(addr));
}
__device__ __forceinline__ void mma_bf16(float* d, const uint32_t* a,
                                         uint32_t b0, uint32_t b1) {
    asm volatile(
        "mma.sync.aligned.m16n8k16.row.col.f32.bf16.bf16.f32 "
        "{%0,%1,%2,%3}, {%4,%5,%6,%7}, {%8,%9}, {%0,%1,%2,%3};"
        : "+f"(d[0]), "+f"(d[1]), "+f"(d[2]), "+f"(d[3])
        : "r"(a[0]), "r"(a[1]), "r"(a[2]), "r"(a[3]), "r"(b0), "r"(b1));
}
#define CP16(dst, src) asm volatile("cp.async.cg.shared.global [%0], [%1], 16;" :: "r"(dst), "l"(src))
#define CP_COMMIT()    asm volatile("cp.async.commit_group;" ::: "memory")
#define CP_WAIT(n)     asm volatile("cp.async.wait_group %0;" :: "n"(n) : "memory")

__device__ __forceinline__ void split1(float x, __nv_bfloat16& h, __nv_bfloat16& l) {
    h = __float2bfloat16(x);
    l = __float2bfloat16(x - __bfloat162float(h));
}

// ---------------------------------------------------------------------------
// ln_kernel: warp-per-row LayerNorm (unchanged)
// ---------------------------------------------------------------------------
__global__ __launch_bounds__(256) void ln_kernel(
    const float* __restrict__ m, const float* __restrict__ gamma,
    const float* __restrict__ beta)
{
    const int row  = blockIdx.x * 8 + (threadIdx.x >> 5);
    const int lane = threadIdx.x & 31;
    const size_t base = (size_t)row * 256 + lane * 8;

    const float4 v0 = *reinterpret_cast<const float4*>(m + base);
    const float4 v1 = *reinterpret_cast<const float4*>(m + base + 4);
    float x[8] = {v0.x, v0.y, v0.z, v0.w, v1.x, v1.y, v1.z, v1.w};

    float s = 0.f, q = 0.f;
#pragma unroll
    for (int c = 0; c < 8; c++) { s += x[c]; q += x[c] * x[c]; }
#pragma unroll
    for (int o = 16; o > 0; o >>= 1) {
        s += __shfl_xor_sync(0xffffffffu, s, o);
        q += __shfl_xor_sync(0xffffffffu, q, o);
    }
    const float mean = s * (1.f / 256.f);
    const float var  = q * (1.f / 256.f) - mean * mean;
    const float rstd = rsqrtf(var + 1e-5f);

    const float4 g0 = *reinterpret_cast<const float4*>(gamma + lane * 8);
    const float4 g1 = *reinterpret_cast<const float4*>(gamma + lane * 8 + 4);
    const float4 b0 = *reinterpret_cast<const float4*>(beta + lane * 8);
    const float4 b1 = *reinterpret_cast<const float4*>(beta + lane * 8 + 4);
    const float gm[8] = {g0.x, g0.y, g0.z, g0.w, g1.x, g1.y, g1.z, g1.w};
    const float bt[8] = {b0.x, b0.y, b0.z, b0.w, b1.x, b1.y, b1.z, b1.w};

    __nv_bfloat16 hb[8], lb[8];
#pragma unroll
    for (int c = 0; c < 8; c++) {
        const float y = (x[c] - mean) * rstd * gm[c] + bt[c];
        split1(y, hb[c], lb[c]);
    }
    *reinterpret_cast<uint4*>(g_Xh + base) = *reinterpret_cast<const uint4*>(hb);
    *reinterpret_cast<uint4*>(g_Xl + base) = *reinterpret_cast<const uint4*>(lb);
}

// ---------------------------------------------------------------------------
// Prep: pair-mask table + Wo^T bf16 split + [Wa|Wb]^T bf16 split (unchanged)
// ---------------------------------------------------------------------------
__global__ __launch_bounds__(256) void prep_kernel(
    const float* __restrict__ mask, const float* __restrict__ Wo,
    const float* __restrict__ Wa, const float* __restrict__ Wb)
{
    const int t = threadIdx.x;
    if (blockIdx.x < 256) {
        const int i = blockIdx.x, j = t;
        float s = 0.f;
        for (int n = 0; n < NN; n++) s += mask[n * LL + i] * mask[n * LL + j];
        g_pm[i * LL + j] = s;
    } else if (blockIdx.x < 320) {
        const int b = blockIdx.x - 256;
#pragma unroll
        for (int v = 0; v < 8; v++) {
            const int e = b * 2048 + v * 256 + t;
            const float val = Wo[e];
            const int k = e >> 7, z = e & 127;
            __nv_bfloat16 hi, lo;
            split1(val, hi, lo);
            g_Woh[z * 1024 + k] = hi;
            g_Wol[z * 1024 + k] = lo;
        }
    } else {
        const int idx = (blockIdx.x - 320) * 256 + t;
        const int o = idx >> 8, k = idx & 255;
        const float val = (o < 32) ? Wa[k * 32 + o] : Wb[k * 32 + (o - 32)];
        __nv_bfloat16 hi, lo;
        split1(val, hi, lo);
        g_Wth[o * 256 + k] = hi;
        g_Wtl[o * 256 + k] = lo;
    }
}

// ---------------------------------------------------------------------------
// proj_kernel (unchanged from R9)
// ---------------------------------------------------------------------------
#define P_XH   0
#define P_XL   67584
#define P_WH   135168
#define P_WL   168960
#define P_MASK 202752
#define P_SMEM 203264

__global__ __launch_bounds__(512) void proj_kernel(
    const float* __restrict__ mask,
    const float* __restrict__ ba, const float* __restrict__ bb)
{
    extern __shared__ char smem[];
    const uint32_t sb = smem_u32(smem);
    const int tid  = threadIdx.x;
    const int lane = tid & 31;
    const int wid  = tid >> 5;
    const int i = blockIdx.x;

#pragma unroll
    for (int v = 0; v < 16; v++) {
        const int idx = v * 512 + tid;
        const int buf = idx >> 12;
        const int rem = idx & 4095;
        const int rown = rem >> 5, q = rem & 31;
        const __nv_bfloat16* src = (buf ? g_Xl : g_Xh) +
            (size_t)(rown * 256 + i) * 256 + q * 8;
        CP16(sb + (buf ? P_XL : P_XH) + rown * 528 + q * 16, src);
    }
#pragma unroll
    for (int v = 0; v < 8; v++) {
        const int idx = v * 512 + tid;
        const int buf = idx >> 11;
        const int rem = idx & 2047;
        const int rowo = rem >> 5, q = rem & 31;
        const __nv_bfloat16* src = (buf ? g_Wtl : g_Wth) + rowo * 256 + q * 8;
        CP16(sb + (buf ? P_WL : P_WH) + rowo * 528 + q * 16, src);
    }
    CP_COMMIT();

    if (tid < 128)
        *reinterpret_cast<float*>(smem + P_MASK + tid * 4) = mask[tid * LL + i];

    CP_WAIT(0);
    __syncthreads();

    const int wm = wid >> 2, wn = wid & 3;
    float acc[2][2][4];
#pragma unroll
    for (int fm = 0; fm < 2; fm++)
#pragma unroll
        for (int fn = 0; fn < 2; fn++)
#pragma unroll
            for (int e = 0; e < 4; e++) acc[fm][fn][e] = 0.f;

    const uint32_t rofs = (uint32_t)((lane & 15) * 528 + (lane >> 4) * 16);
    const uint32_t aXh = sb + P_XH + wm * 32 * 528 + rofs;
    const uint32_t aXl = sb + P_XL + wm * 32 * 528 + rofs;
    const uint32_t aWh = sb + P_WH + wn * 16 * 528 + rofs;
    const uint32_t aWl = sb + P_WL + wn * 16 * 528 + rofs;

#pragma unroll
    for (int ks = 0; ks < 16; ks++) {
        uint32_t X_h[2][4], X_l[2][4], W_h[4], W_l[4];
        ldsm4(X_h[0], aXh + ks * 32);
        ldsm4(X_h[1], aXh + 16 * 528 + ks * 32);
        ldsm4(X_l[0], aXl + ks * 32);
        ldsm4(X_l[1], aXl + 16 * 528 + ks * 32);
        ldsm4(W_h, aWh + ks * 32);
        ldsm4(W_l, aWl + ks * 32);
#pragma unroll
        for (int fm = 0; fm < 2; fm++)
#pragma unroll
            for (int fn = 0; fn < 2; fn++) {
                const uint32_t bh0 = W_h[fn], bh1 = W_h[fn + 2];
                const uint32_t bl0 = W_l[fn], bl1 = W_l[fn + 2];
                mma_bf16(acc[fm][fn], X_h[fm], bh0, bh1);
                mma_bf16(acc[fm][fn], X_h[fm], bl0, bl1);
                mma_bf16(acc[fm][fn], X_l[fm], bh0, bh1);
            }
    }

    __syncthreads();

    float* sOut = reinterpret_cast<float*>(smem);
    const float* sMask = reinterpret_cast<const float*>(smem + P_MASK);
#pragma unroll
    for (int fm = 0; fm < 2; fm++)
#pragma unroll
        for (int fn = 0; fn < 2; fn++)
#pragma unroll
            for (int e = 0; e < 4; e++) {
                const int n_loc = wm * 32 + fm * 16 + (lane >> 2) + (e >> 1) * 8;
                const int o     = wn * 16 + fn * 8 + (lane & 3) * 2 + (e & 1);
                const float bias = (o < 32) ? ba[o] : bb[o - 32];
                sOut[o * 132 + n_loc] = (acc[fm][fn][e] + bias) * sMask[n_loc];
            }
    __syncthreads();

    {
        const int o  = tid >> 3;
        const int n0 = (tid & 7) * 16;
        __nv_bfloat16 hb[16], lb[16];
#pragma unroll
        for (int c = 0; c < 16; c++)
            split1(sOut[o * 132 + n0 + c], hb[c], lb[c]);
        __nv_bfloat16* dh = ((o < 32) ? g_Ah : g_Bh) + (size_t)(i * 32 + (o & 31)) * 128 + n0;
        __nv_bfloat16* dl = ((o < 32) ? g_Al : g_Bl) + (size_t)(i * 32 + (o & 31)) * 128 + n0;
        reinterpret_cast<uint4*>(dh)[0] = reinterpret_cast<const uint4*>(hb)[0];
        reinterpret_cast<uint4*>(dh)[1] = reinterpret_cast<const uint4*>(hb)[1];
        reinterpret_cast<uint4*>(dl)[0] = reinterpret_cast<const uint4*>(lb)[0];
        reinterpret_cast<uint4*>(dl)[1] = reinterpret_cast<const uint4*>(lb)[1];
    }
}

// ---------------------------------------------------------------------------
// Fused kernel, 256x128 tile (32 pairs).
// Phase A: GEMM in regs (barrier-pipelined, as R10).
// Phase B: barrier-free per-warp Wo streaming with HOISTED addressing:
//   - 4 per-lane global src pointers, bumped +128B per chunk (no index math)
//   - 4 constant smem dst offsets (stage base alternates)
//   - ck loop fully unrolled; A fragments double-buffered in registers
//     (ldsm for ck+1 issued before ck's MMAs -> LDS latency hidden)
//   One __syncthreads between mainloop and k-split reduction (R12 fix).
// SMEM layout identical to R12.
// ---------------------------------------------------------------------------
#define F_AH   0
#define F_AL   69632
#define F_BH   139264
#define F_BL   174080
#define OFFO   65536
#define OFFOL  (OFFO + 66048)
#define OFFPM  197632
#define F_SMEM 208896

__global__ __launch_bounds__(512) void fused_kernel(
    const float* __restrict__ bo, float* __restrict__ out)
{
    extern __shared__ char smem[];
    const uint32_t sb = smem_u32(smem);
    const int tid  = threadIdx.x;
    const int lane = tid & 31;
    const int wid  = tid >> 5;
    const int bm = blockIdx.y, bn = blockIdx.x;   // bm 0..31, bn 0..63
    const int i0 = bm * 8, j0 = bn * 4;

    // ======================= Phase A (as R10) ===============================
#pragma unroll
    for (int kh = 0; kh < 2; kh++) {
#pragma unroll
        for (int v = 0; v < 12; v++) {
            const int idx = v * 512 + tid;
            if (idx < 4096) {
                const int buf = idx >> 11;
                const int rem = idx & 2047;
                const int row = rem >> 3, q = rem & 7;
                const __nv_bfloat16* src = (buf ? g_Al : g_Ah) +
                    (size_t)(bm * 256 + row) * 128 + kh * 64 + q * 8;
                CP16(sb + (buf ? F_AL : F_AH) + row * 272 + kh * 128 + q * 16, src);
            } else {
                const int r2  = idx - 4096;
                const int buf = r2 >> 10;
                const int rem = r2 & 1023;
                const int row = rem >> 3, q = rem & 7;
                const __nv_bfloat16* src = (buf ? g_Bl : g_Bh) +
                    (size_t)(bn * 128 + row) * 128 + kh * 64 + q * 8;
                CP16(sb + (buf ? F_BL : F_BH) + row * 272 + kh * 128 + q * 16, src);
            }
        }
        CP_COMMIT();
    }

    const int wm = wid >> 1, wn = wid & 1;
    float acc[2][8][4];
#pragma unroll
    for (int fm = 0; fm < 2; fm++)
#pragma unroll
        for (int fn = 0; fn < 8; fn++)
#pragma unroll
            for (int e = 0; e < 4; e++) acc[fm][fn][e] = 0.f;

    const uint32_t rofsA = (uint32_t)((lane & 15) * 272 + (lane >> 4) * 16);
    const uint32_t aAh = sb + F_AH + wm * 32 * 272 + rofsA;
    const uint32_t aAl = sb + F_AL + wm * 32 * 272 + rofsA;
    const uint32_t aBh = sb + F_BH + wn * 64 * 272 + rofsA;
    const uint32_t aBl = sb + F_BL + wn * 64 * 272 + rofsA;

    CP_WAIT(1);
    __syncthreads();

#pragma unroll
    for (int ks = 0; ks < 8; ks++) {
        if (ks == 4) { CP_WAIT(0); __syncthreads(); }
        uint32_t A_h[2][4], A_l[2][4];
        ldsm4(A_h[0], aAh + ks * 32);
        ldsm4(A_h[1], aAh + 16 * 272 + ks * 32);
        ldsm4(A_l[0], aAl + ks * 32);
        ldsm4(A_l[1], aAl + 16 * 272 + ks * 32);
#pragma unroll
        for (int bh2 = 0; bh2 < 2; bh2++) {
            uint32_t B_h[2][4], B_l[2][4];
            const uint32_t bo0 = (uint32_t)(bh2 * 32 * 272 + ks * 32);
            ldsm4(B_h[0], aBh + bo0);
            ldsm4(B_h[1], aBh + 16 * 272 + bo0);
            ldsm4(B_l[0], aBl + bo0);
            ldsm4(B_l[1], aBl + 16 * 272 + bo0);
#pragma unroll
            for (int fm = 0; fm < 2; fm++)
#pragma unroll
                for (int fl = 0; fl < 4; fl++) {
                    const int fn = bh2 * 4 + fl;
                    const uint32_t bh0 = B_h[fl >> 1][fl & 1];
                    const uint32_t bh1 = B_h[fl >> 1][(fl & 1) + 2];
                    const uint32_t bl0 = B_l[fl >> 1][fl & 1];
                    const uint32_t bl1 = B_l[fl >> 1][(fl & 1) + 2];
                    mma_bf16(acc[fm][fn], A_h[fm], bh0, bh1);
                    mma_bf16(acc[fm][fn], A_h[fm], bl0, bl1);
                    mma_bf16(acc[fm][fn], A_l[fm], bh0, bh1);
                }
        }
    }

    __syncthreads();   // all A/B smem reads done; stage region reusable

    // ---- hoisted Wo streaming state ----
    const int wn2 = wid & 3;
    const int kc  = wid >> 2;
    const uint32_t wstage0 = sb + wid * 2048;
    const int rv = lane >> 1, hv = lane & 1;
    const uint32_t hsv = (uint32_t)((hv ^ ((rv >> 2) & 1)) << 4);
    const __nv_bfloat16* wsrc0 = g_Woh + (size_t)(wn2 * 32 + rv) * 1024 + kc * 16 + hv * 8;
    const __nv_bfloat16* wsrc1 = g_Woh + (size_t)(wn2 * 32 + 16 + rv) * 1024 + kc * 16 + hv * 8;
    const __nv_bfloat16* wsrc2 = g_Wol + (size_t)(wn2 * 32 + rv) * 1024 + kc * 16 + hv * 8;
    const __nv_bfloat16* wsrc3 = g_Wol + (size_t)(wn2 * 32 + 16 + rv) * 1024 + kc * 16 + hv * 8;
    const uint32_t d0 = (uint32_t)(rv * 32) + hsv;
    const uint32_t d1 = (uint32_t)((16 + rv) * 32) + hsv;

    // prologue: stream chunks 0 (stage 0) and 1 (stage 1)
#pragma unroll
    for (int pre = 0; pre < 2; pre++) {
        const uint32_t stb = wstage0 + pre * 32768;
        CP16(stb + d0, wsrc0);
        CP16(stb + d1, wsrc1);
        CP16(stb + 1024 + d0, wsrc2);
        CP16(stb + 1024 + d1, wsrc3);
        CP_COMMIT();
        wsrc0 += 64; wsrc1 += 64; wsrc2 += 64; wsrc3 += 64;
    }

    // ---- O spill: pair p = wm*4 + wn*2 + (fn>>2), k = c*32 + d ----
#pragma unroll
    for (int fm = 0; fm < 2; fm++)
#pragma unroll
        for (int fn = 0; fn < 8; fn++) {
            const int p = wm * 4 + wn * 2 + (fn >> 2);
            char* oh = smem + OFFO  + p * 2064;
            char* ol = smem + OFFOL + p * 2064;
#pragma unroll
            for (int half = 0; half < 2; half++) {
                const int c = fm * 16 + (lane >> 2) + half * 8;
                const int d = (fn & 3) * 8 + (lane & 3) * 2;
                const int k = c * 32 + d;
                __nv_bfloat162 h2, l2;
                split1(acc[fm][fn][half * 2 + 0], h2.x, l2.x);
                split1(acc[fm][fn][half * 2 + 1], h2.y, l2.y);
                *reinterpret_cast<__nv_bfloat162*>(oh + 2 * k) = h2;
                *reinterpret_cast<__nv_bfloat162*>(ol + 2 * k) = l2;
            }
        }
    if (tid < 32) {
        const int ii = i0 + (tid >> 2), jj = j0 + (tid & 3);
        *reinterpret_cast<float*>(smem + OFFPM + tid * 4) =
            1.f / (g_pm[ii * LL + jj] + 1e-8f);
    }
    __syncthreads();   // O + pm visible to all warps

    // ======================= Phase B: barrier-free, unrolled ================
    float acc2[2][4][4];
#pragma unroll
    for (int fm = 0; fm < 2; fm++)
#pragma unroll
        for (int fn = 0; fn < 4; fn++)
#pragma unroll
            for (int e = 0; e < 4; e++) acc2[fm][fn][e] = 0.f;

    const uint32_t aOh = sb + OFFO + (uint32_t)((lane & 15) * 2064 + (lane >> 4) * 16);
    const uint32_t aOl = aOh + 66048;
    const int rB  = lane & 15;
    const int cbB = lane >> 4;
    const uint32_t bofs = (uint32_t)(rB * 32 + ((cbB ^ ((rB >> 2) & 1)) << 4));

    // A fragments double-buffered in registers
    uint32_t AH[2][2][4], AL[2][2][4];
    {
        const uint32_t ao = (uint32_t)(kc * 32);
        ldsm4(AH[0][0], aOh + ao);
        ldsm4(AH[0][1], aOh + 16 * 2064 + ao);
        ldsm4(AL[0][0], aOl + ao);
        ldsm4(AL[0][1], aOl + 16 * 2064 + ao);
    }

#pragma unroll
    for (int ck = 0; ck < 16; ck++) {
        const int pp = ck & 1;
        if (ck < 15) {   // prefetch A frags for ck+1 (independent of cp.async)
            const uint32_t ao = (uint32_t)((ck + 1) * 128 + kc * 32);
            ldsm4(AH[pp ^ 1][0], aOh + ao);
            ldsm4(AH[pp ^ 1][1], aOh + 16 * 2064 + ao);
            ldsm4(AL[pp ^ 1][0], aOl + ao);
            ldsm4(AL[pp ^ 1][1], aOl + 16 * 2064 + ao);
        }
        if (ck == 15) CP_WAIT(0); else CP_WAIT(1);
        __syncwarp();

        uint32_t B_h[2][4], B_l[2][4];
        const uint32_t wb = wstage0 + pp * 32768;
        ldsm4(B_h[0], wb + bofs);
        ldsm4(B_h[1], wb + 512 + bofs);
        ldsm4(B_l[0], wb + 1024 + bofs);
        ldsm4(B_l[1], wb + 1536 + bofs);

        if (ck + 2 < 16) {   // stream chunk ck+2 into stage pp
            CP16(wb + d0, wsrc0);
            CP16(wb + d1, wsrc1);
            CP16(wb + 1024 + d0, wsrc2);
            CP16(wb + 1024 + d1, wsrc3);
            CP_COMMIT();
            wsrc0 += 64; wsrc1 += 64; wsrc2 += 64; wsrc3 += 64;
        }

#pragma unroll
        for (int fm = 0; fm < 2; fm++)
#pragma unroll
            for (int fn = 0; fn < 4; fn++) {
                const uint32_t bh0 = B_h[fn >> 1][fn & 1];
                const uint32_t bh1 = B_h[fn >> 1][(fn & 1) + 2];
                const uint32_t bl0 = B_l[fn >> 1][fn & 1];
                const uint32_t bl1 = B_l[fn >> 1][(fn & 1) + 2];
                mma_bf16(acc2[fm][fn], AH[pp][fm], bh0, bh1);
                mma_bf16(acc2[fm][fn], AH[pp][fm], bl0, bl1);
                mma_bf16(acc2[fm][fn], AL[pp][fm], bh0, bh1);
            }
    }

    // all warps must finish reading stage buffers before reduction reuses them
    __syncthreads();

    // ---- k-split reduction via smem [0, 49152) ----
    float* red = reinterpret_cast<float*>(smem);
    if (kc > 0) {
#pragma unroll
        for (int fm = 0; fm < 2; fm++)
#pragma unroll
            for (int fn = 0; fn < 4; fn++)
#pragma unroll
                for (int e = 0; e < 4; e++) {
                    const int p = fm * 16 + (lane >> 2) + (e >> 1) * 8;
                    const int z = wn2 * 32 + fn * 8 + (lane & 3) * 2 + (e & 1);
                    red[(kc - 1) * 4096 + p * 128 + z] = acc2[fm][fn][e];
                }
    }
    __syncthreads();
    if (kc == 0) {
        const float* pmv = reinterpret_cast<const float*>(smem + OFFPM);
#pragma unroll
        for (int fm = 0; fm < 2; fm++)
#pragma unroll
            for (int fn = 0; fn < 4; fn++)
#pragma unroll
                for (int e = 0; e < 4; e++) {
                    const int p = fm * 16 + (lane >> 2) + (e >> 1) * 8;
                    const int z = wn2 * 32 + fn * 8 + (lane & 3) * 2 + (e & 1);
                    acc2[fm][fn][e] += red[p * 128 + z]
                                     + red[4096 + p * 128 + z]
                                     + red[8192 + p * 128 + z];
                }
#pragma unroll
        for (int fm = 0; fm < 2; fm++)
#pragma unroll
            for (int fn = 0; fn < 4; fn++)
#pragma unroll
                for (int prow = 0; prow < 2; prow++) {
                    const int p  = fm * 16 + (lane >> 2) + prow * 8;
                    const int ii = i0 + (p >> 2), jj = j0 + (p & 3);
                    const float inv = pmv[p];
                    const int z = wn2 * 32 + fn * 8 + (lane & 3) * 2;
                    float2 res;
                    res.x = acc2[fm][fn][prow * 2 + 0] * inv + bo[z];
                    res.y = acc2[fm][fn][prow * 2 + 1] * inv + bo[z + 1];
                    *reinterpret_cast<float2*>(out + (size_t)(ii * LL + jj) * CZ + z) = res;
                }
    }
}

// ---------------------------------------------------------------------------
extern "C" void kernel_launch(void* const* d_in, const int* in_sizes, int n_in,
                              void* d_out, int out_size)
{
    const float* m     = (const float*)d_in[0];
    const float* mask  = (const float*)d_in[1];
    const float* gamma = (const float*)d_in[2];
    const float* beta  = (const float*)d_in[3];
    const float* Wa    = (const float*)d_in[4];
    const float* ba    = (const float*)d_in[5];
    const float* Wb    = (const float*)d_in[6];
    const float* bb    = (const float*)d_in[7];
    const float* Wo    = (const float*)d_in[8];
    const float* bo    = (const float*)d_in[9];
    float* out = (float*)d_out;

    cudaFuncSetAttribute(proj_kernel,  cudaFuncAttributeMaxDynamicSharedMemorySize, P_SMEM);
    cudaFuncSetAttribute(fused_kernel, cudaFuncAttributeMaxDynamicSharedMemorySize, F_SMEM);

    ln_kernel<<<4096, 256>>>(m, gamma, beta);
    prep_kernel<<<384, 256>>>(mask, Wo, Wa, Wb);
    proj_kernel<<<256, 512, P_SMEM>>>(mask, ba, bb);
    fused_kernel<<<dim3(64, 32), 512, F_SMEM>>>(bo, out);
}